// round 1
// baseline (speedup 1.0000x reference)
#include <cuda_runtime.h>

#define TOK 64
#define CDIM 96
#define HH 256
#define WWI 256

// SMEM plan (floats):
//  ws   : 288*97  qkv_w (staged), later out_w (96*97) reuses front
//  xs   : 64*97   x window, later scores (64*65)
//  qs   : 64*97   q, later o = attn@v + lepe
//  ks   : 64*97   k, later final-out staging
//  vs   : 64*97   v
//  wb   : 288     qkv_b
//  cw   : 864     conv_w (96*9)
//  cb   : 96      conv_b
//  ob   : 96      out_b
#define SMEM_FLOATS (288*97 + 4*64*97 + 288 + 864 + 96 + 96)
#define SMEM_BYTES  (SMEM_FLOATS * 4)

__global__ __launch_bounds__(256, 1)
void vitblock_fused(const float* __restrict__ x,
                    const float* __restrict__ qkv_w,
                    const float* __restrict__ qkv_b,
                    const float* __restrict__ conv_w,
                    const float* __restrict__ conv_b,
                    const float* __restrict__ out_w,
                    const float* __restrict__ out_b,
                    float* __restrict__ out)
{
    extern __shared__ float sm[];
    float* ws = sm;                  // 288*97
    float* xs = ws + 288*97;         // 64*97
    float* qs = xs + 64*97;
    float* ks = qs + 64*97;
    float* vs = ks + 64*97;
    float* wb = vs + 64*97;          // 288
    float* cw = wb + 288;            // 864
    float* cb = cw + 864;            // 96
    float* ob = cb + 96;             // 96

    const int tid = threadIdx.x;
    const int win = blockIdx.x;
    const int b   = win >> 10;          // 1024 windows per batch image
    const int wh  = (win >> 5) & 31;
    const int wv  = win & 31;
    const int h0  = wh * 8, w0 = wv * 8;

    // ---- Phase 1: stage x window + weights ----
    const float* xbase = x + (size_t)b * CDIM * HH * WWI;
    for (int idx = tid; idx < CDIM * TOK; idx += 256) {
        int c = idx >> 6;           // /64
        int t = idx & 63;
        int i = t >> 3, j = t & 7;
        xs[t * 97 + c] = xbase[(c * HH + h0 + i) * WWI + w0 + j];
    }
    for (int idx = tid; idx < 288 * CDIM; idx += 256) {
        int o = idx / 96, c = idx % 96;
        ws[o * 97 + c] = qkv_w[idx];
    }
    for (int idx = tid; idx < 288; idx += 256) wb[idx] = qkv_b[idx];
    for (int idx = tid; idx < 864; idx += 256) cw[idx] = conv_w[idx];
    if (tid < 96) { cb[tid] = conv_b[tid]; ob[tid] = out_b[tid]; }
    __syncthreads();

    const int tg = tid >> 5;   // warp id -> token group (8 tokens)
    const int og = tid & 31;   // lane -> output column group
    const int t0 = tg * 8;

    // ---- Phase 2: QKV projection (64x288 = [64x96] @ w^T) ----
    {
        float acc[8][9];
        #pragma unroll
        for (int k = 0; k < 9; k++) {
            float bv = wb[og + 32 * k];
            #pragma unroll
            for (int i = 0; i < 8; i++) acc[i][k] = bv;
        }
        #pragma unroll 2
        for (int c = 0; c < 96; c++) {
            float xv[8], wvv[9];
            #pragma unroll
            for (int i = 0; i < 8; i++) xv[i] = xs[(t0 + i) * 97 + c];
            #pragma unroll
            for (int k = 0; k < 9; k++) wvv[k] = ws[(og + 32 * k) * 97 + c];
            #pragma unroll
            for (int i = 0; i < 8; i++)
                #pragma unroll
                for (int k = 0; k < 9; k++)
                    acc[i][k] += xv[i] * wvv[k];
        }
        #pragma unroll
        for (int k = 0; k < 9; k++) {
            float* dst = (k < 3) ? qs : (k < 6) ? ks : vs;
            int col = og + 32 * (k % 3);
            #pragma unroll
            for (int i = 0; i < 8; i++) dst[(t0 + i) * 97 + col] = acc[i][k];
        }
    }
    __syncthreads();

    // ---- Phase 3: stage out_w into ws (qkv_w dead); scores = q@k^T * scale ----
    float* sc = xs;   // 64x65, xs dead
    for (int idx = tid; idx < 96 * 96; idx += 256) {
        int o = idx / 96, c = idx % 96;
        ws[o * 97 + c] = out_w[idx];
    }
    {
        const int ng = tid >> 4, mg = tid & 15;
        const int n0 = ng * 4, m0 = mg * 4;
        float acc[4][4];
        #pragma unroll
        for (int a = 0; a < 4; a++)
            #pragma unroll
            for (int r = 0; r < 4; r++) acc[a][r] = 0.f;
        #pragma unroll 2
        for (int c = 0; c < 96; c++) {
            float qv[4], kv[4];
            #pragma unroll
            for (int a = 0; a < 4; a++) qv[a] = qs[(n0 + a) * 97 + c];
            #pragma unroll
            for (int r = 0; r < 4; r++) kv[r] = ks[(m0 + r) * 97 + c];
            #pragma unroll
            for (int a = 0; a < 4; a++)
                #pragma unroll
                for (int r = 0; r < 4; r++) acc[a][r] += qv[a] * kv[r];
        }
        const float scale = 0.10206207261596575f;   // 1/sqrt(96)
        #pragma unroll
        for (int a = 0; a < 4; a++)
            #pragma unroll
            for (int r = 0; r < 4; r++)
                sc[(n0 + a) * 65 + m0 + r] = acc[a][r] * scale;
    }
    __syncthreads();

    // ---- Phase 4: row softmax (4 lanes per row) ----
    {
        int row = tid >> 2, q4 = tid & 3;
        float* r = sc + row * 65 + q4 * 16;
        float mx = -1e30f;
        #pragma unroll
        for (int m = 0; m < 16; m++) mx = fmaxf(mx, r[m]);
        mx = fmaxf(mx, __shfl_xor_sync(0xffffffffu, mx, 1));
        mx = fmaxf(mx, __shfl_xor_sync(0xffffffffu, mx, 2));
        float ev[16], sum = 0.f;
        #pragma unroll
        for (int m = 0; m < 16; m++) { ev[m] = expf(r[m] - mx); sum += ev[m]; }
        sum += __shfl_xor_sync(0xffffffffu, sum, 1);
        sum += __shfl_xor_sync(0xffffffffu, sum, 2);
        float inv = 1.0f / sum;
        #pragma unroll
        for (int m = 0; m < 16; m++) r[m] = ev[m] * inv;
    }
    __syncthreads();

    // ---- Phase 5: o = attn@v + LePE(conv3x3 depthwise on v) + conv_b -> os (qs region) ----
    float* os = qs;   // q dead after scores
    {
        float acc[8][3];
        #pragma unroll
        for (int k = 0; k < 3; k++) {
            float bv = cb[og + 32 * k];
            #pragma unroll
            for (int i = 0; i < 8; i++) acc[i][k] = bv;
        }
        #pragma unroll 2
        for (int m = 0; m < 64; m++) {
            float av[8], vvv[3];
            #pragma unroll
            for (int i = 0; i < 8; i++) av[i] = sc[(t0 + i) * 65 + m];
            #pragma unroll
            for (int k = 0; k < 3; k++) vvv[k] = vs[m * 97 + og + 32 * k];
            #pragma unroll
            for (int i = 0; i < 8; i++)
                #pragma unroll
                for (int k = 0; k < 3; k++) acc[i][k] += av[i] * vvv[k];
        }
        // LePE taps: token t0+i -> (y=tg, x=i) within 8x8 window, zero pad
        #pragma unroll
        for (int k = 0; k < 3; k++) {
            int c = og + 32 * k;
            float w9[9];
            #pragma unroll
            for (int q = 0; q < 9; q++) w9[q] = cw[c * 9 + q];
            #pragma unroll
            for (int i = 0; i < 8; i++) {
                int y = tg, xx = i;
                float s = 0.f;
                #pragma unroll
                for (int dy = -1; dy <= 1; dy++) {
                    int yy = y + dy;
                    if (yy < 0 || yy > 7) continue;
                    #pragma unroll
                    for (int dx = -1; dx <= 1; dx++) {
                        int xc = xx + dx;
                        if (xc < 0 || xc > 7) continue;
                        s += vs[(yy * 8 + xc) * 97 + c] * w9[(dy + 1) * 3 + dx + 1];
                    }
                }
                acc[i][k] += s;
            }
        }
        #pragma unroll
        for (int k = 0; k < 3; k++) {
            int c = og + 32 * k;
            #pragma unroll
            for (int i = 0; i < 8; i++) os[(t0 + i) * 97 + c] = acc[i][k];
        }
    }
    __syncthreads();

    // ---- Phase 6: final projection -> outs (ks region) ----
    float* outs = ks;
    {
        float acc[8][3];
        #pragma unroll
        for (int k = 0; k < 3; k++) {
            float bv = ob[og + 32 * k];
            #pragma unroll
            for (int i = 0; i < 8; i++) acc[i][k] = bv;
        }
        #pragma unroll 2
        for (int c = 0; c < 96; c++) {
            float ov[8], wvv[3];
            #pragma unroll
            for (int i = 0; i < 8; i++) ov[i] = os[(t0 + i) * 97 + c];
            #pragma unroll
            for (int k = 0; k < 3; k++) wvv[k] = ws[(og + 32 * k) * 97 + c];
            #pragma unroll
            for (int i = 0; i < 8; i++)
                #pragma unroll
                for (int k = 0; k < 3; k++) acc[i][k] += ov[i] * wvv[k];
        }
        #pragma unroll
        for (int k = 0; k < 3; k++) {
            int oc = og + 32 * k;
            #pragma unroll
            for (int i = 0; i < 8; i++) outs[(t0 + i) * 97 + oc] = acc[i][k];
        }
    }
    __syncthreads();

    // ---- Phase 7: coalesced writeout [B,C,H,W] ----
    float* obase = out + (size_t)b * CDIM * HH * WWI;
    for (int idx = tid; idx < CDIM * TOK; idx += 256) {
        int oc = idx >> 6;
        int t  = idx & 63;
        int i  = t >> 3, j = t & 7;
        obase[(oc * HH + h0 + i) * WWI + w0 + j] = outs[t * 97 + oc];
    }
}

extern "C" void kernel_launch(void* const* d_in, const int* in_sizes, int n_in,
                              void* d_out, int out_size) {
    const float* x      = (const float*)d_in[0];
    const float* qkv_w  = (const float*)d_in[1];
    const float* qkv_b  = (const float*)d_in[2];
    const float* conv_w = (const float*)d_in[3];
    const float* conv_b = (const float*)d_in[4];
    const float* out_w  = (const float*)d_in[5];
    const float* out_b  = (const float*)d_in[6];
    float* out = (float*)d_out;

    cudaFuncSetAttribute(vitblock_fused,
                         cudaFuncAttributeMaxDynamicSharedMemorySize, SMEM_BYTES);
    vitblock_fused<<<8192, 256, SMEM_BYTES>>>(x, qkv_w, qkv_b, conv_w, conv_b,
                                              out_w, out_b, out);
}

// round 3
// speedup vs baseline: 2.3980x; 2.3980x over previous
#include <cuda_runtime.h>
#include <cuda_bf16.h>
#include <cstdint>

#define SCALE_Q 0.10206207261596575f   // 1/sqrt(96)
#define XS 104   // bf16 row stride for 96-col operand tiles (conflict-free ldmatrix)
#define VS 136   // Vt row stride (tok dim 128 + 8)
#define FS 98    // fp32 staging stride

// ---- smem byte offsets ----
#define O_QB   0          // qkv_b 288 f
#define O_CW   1152       // cwT[9][96] 864 f
#define O_CB   4608       // conv_b 96 f
#define O_OB   4992       // out_b 96 f
#define O_X    5376       // Xhi/Xlo bf16 [128][104]x2 = 53248; later v fp32 [128][98]; later outstage
#define XLO    26624
#define O_W    58624      // W chunk hi/lo [96][104]x2 = 39936
#define WLO    19968
#define O_K    98560      // K hi/lo [128][104]x2 = 53248
#define KLO    26624
#define O_VT   151808     // Vt hi/lo [96][136]x2 = 52224
#define VTLO   26112
#define SMEM_BYTES 204032

__device__ __forceinline__ uint32_t smem_u32(const void* p) {
    uint32_t a;
    asm("{ .reg .u64 t; cvta.to.shared.u64 t, %1; cvt.u32.u64 %0, t; }" : "=r"(a) : "l"(p));
    return a;
}
__device__ __forceinline__ void ldm4(uint32_t a, uint32_t* r) {
    asm volatile("ldmatrix.sync.aligned.m8n8.x4.shared.b16 {%0,%1,%2,%3}, [%4];"
                 : "=r"(r[0]), "=r"(r[1]), "=r"(r[2]), "=r"(r[3]) : "r"(a));
}
#define MMA4(D, A, B0, B1) \
    asm volatile("mma.sync.aligned.m16n8k16.row.col.f32.bf16.bf16.f32 " \
        "{%0,%1,%2,%3},{%4,%5,%6,%7},{%8,%9},{%0,%1,%2,%3};" \
        : "+f"((D)[0]), "+f"((D)[1]), "+f"((D)[2]), "+f"((D)[3]) \
        : "r"((A)[0]), "r"((A)[1]), "r"((A)[2]), "r"((A)[3]), "r"(B0), "r"(B1))

__device__ __forceinline__ uint32_t bpack(__nv_bfloat16 a, __nv_bfloat16 b) {
    __nv_bfloat162 t = __halves2bfloat162(a, b);   // .x = a (low 16 bits = lower k)
    return *reinterpret_cast<uint32_t*>(&t);
}
__device__ __forceinline__ void split2(float a, float b, uint32_t& h, uint32_t& l) {
    __nv_bfloat16 ha = __float2bfloat16(a), hb = __float2bfloat16(b);
    h = bpack(ha, hb);
    l = bpack(__float2bfloat16(a - __bfloat162float(ha)),
              __float2bfloat16(b - __bfloat162float(hb)));
}

// C[128x96-chunk] += (Xhi+Xlo)·(Whi+Wlo)^T  — A,B both in smem, 6 ksteps, 12 n-tiles
__device__ __forceinline__ void gemm_ss(uint32_t sb, uint32_t aOff, uint32_t bOff,
                                        int arow, int lane, float d[12][4]) {
    const int lr = lane & 15, lc = lane >> 4;
    #pragma unroll
    for (int k = 0; k < 6; k++) {
        uint32_t ah[4], al[4];
        uint32_t aaddr = sb + aOff + (((arow + lr) * XS + k * 16 + lc * 8) << 1);
        ldm4(aaddr, ah);
        ldm4(aaddr + XLO, al);
        #pragma unroll
        for (int np = 0; np < 6; np++) {
            uint32_t bh[4], bl[4];
            uint32_t baddr = sb + bOff + (((np * 16 + lr) * XS + k * 16 + lc * 8) << 1);
            ldm4(baddr, bh);
            ldm4(baddr + WLO, bl);
            MMA4(d[2*np],   ah, bh[0], bh[2]);
            MMA4(d[2*np+1], ah, bh[1], bh[3]);
            MMA4(d[2*np],   ah, bl[0], bl[2]);
            MMA4(d[2*np+1], ah, bl[1], bl[3]);
            MMA4(d[2*np],   al, bh[0], bh[2]);
            MMA4(d[2*np+1], al, bh[1], bh[3]);
        }
    }
}

__device__ __forceinline__ void stage_w(const float* __restrict__ w, char* smem, int tid) {
    #pragma unroll
    for (int it = 0; it < 9; it++) {
        int e = it * 256 + tid;          // 2304 = 96 rows x 24 col-quads
        int o = e / 24, q = e - o * 24;
        float4 v = *(const float4*)(w + o * 96 + q * 4);
        __nv_bfloat16 h0 = __float2bfloat16(v.x), h1 = __float2bfloat16(v.y);
        __nv_bfloat16 h2 = __float2bfloat16(v.z), h3 = __float2bfloat16(v.w);
        uint2 H = { bpack(h0, h1), bpack(h2, h3) };
        uint2 L = { bpack(__float2bfloat16(v.x - __bfloat162float(h0)),
                          __float2bfloat16(v.y - __bfloat162float(h1))),
                    bpack(__float2bfloat16(v.z - __bfloat162float(h2)),
                          __float2bfloat16(v.w - __bfloat162float(h3))) };
        uint32_t off = (uint32_t)(o * XS + q * 4) << 1;
        *(uint2*)(smem + O_W + off) = H;
        *(uint2*)(smem + O_W + WLO + off) = L;
    }
}

__global__ __launch_bounds__(256, 1)
void vitblock_mma(const float* __restrict__ x,
                  const float* __restrict__ qkv_w,
                  const float* __restrict__ qkv_b,
                  const float* __restrict__ conv_w,
                  const float* __restrict__ conv_b,
                  const float* __restrict__ out_w,
                  const float* __restrict__ out_b,
                  float* __restrict__ out)
{
    extern __shared__ char smem[];
    const uint32_t sb = smem_u32(smem);
    const int tid = threadIdx.x;
    const int w = tid >> 5, lane = tid & 31;
    const int lr = lane & 15, lc = lane >> 4;
    const int c2 = (lane & 3) * 2;
    const int r0 = 16 * w + (lane >> 2);
    const int win = w >> 2;

    const int wv0 = (blockIdx.x << 1) & 31;
    const int wh  = (blockIdx.x >> 4) & 31;
    const int bI  = blockIdx.x >> 9;
    const float* xg = x + ((size_t)bI * 96) * 65536 + (size_t)(wh * 8) * 256 + wv0 * 8;

    // ---- P0: stage consts, X, Wq ----
    for (int i = tid; i < 288; i += 256) *(float*)(smem + O_QB + i * 4) = qkv_b[i];
    for (int i = tid; i < 864; i += 256) {
        int ch = i / 9, tap = i - ch * 9;
        *(float*)(smem + O_CW + (tap * 96 + ch) * 4) = conv_w[i];
    }
    if (tid < 96) {
        *(float*)(smem + O_CB + tid * 4) = conv_b[tid];
        *(float*)(smem + O_OB + tid * 4) = out_b[tid];
    }
    #pragma unroll
    for (int it = 0; it < 12; it++) {
        int e = it * 256 + tid;                  // 3072 = 24 c4 x 8 i x 16 jj
        int c4 = e >> 7, i = (e >> 4) & 7, jj = e & 15;
        const float* p = xg + (size_t)(c4 * 4) * 65536 + i * 256 + jj;
        float v0 = p[0], v1 = p[65536], v2 = p[131072], v3 = p[196608];
        int m = ((jj >> 3) << 6) + (i << 3) + (jj & 7);
        __nv_bfloat16 h0 = __float2bfloat16(v0), h1 = __float2bfloat16(v1);
        __nv_bfloat16 h2 = __float2bfloat16(v2), h3 = __float2bfloat16(v3);
        uint2 H = { bpack(h0, h1), bpack(h2, h3) };
        uint2 L = { bpack(__float2bfloat16(v0 - __bfloat162float(h0)),
                          __float2bfloat16(v1 - __bfloat162float(h1))),
                    bpack(__float2bfloat16(v2 - __bfloat162float(h2)),
                          __float2bfloat16(v3 - __bfloat162float(h3))) };
        uint32_t off = (uint32_t)(m * XS + c4 * 4) << 1;
        *(uint2*)(smem + O_X + off) = H;
        *(uint2*)(smem + O_X + XLO + off) = L;
    }
    stage_w(qkv_w, smem, tid);
    __syncthreads();

    // ---- GEMM1a: Q ----
    uint32_t qh[6][4], ql[6][4];
    {
        float d[12][4];
        #pragma unroll
        for (int j = 0; j < 12; j++) { d[j][0]=0.f; d[j][1]=0.f; d[j][2]=0.f; d[j][3]=0.f; }
        gemm_ss(sb, O_X, O_W, 16 * w, lane, d);
        #pragma unroll
        for (int jj = 0; jj < 6; jj++) {
            int ta = 2 * jj, tb = 2 * jj + 1;
            float2 ba = *(float2*)(smem + O_QB + (8 * ta + c2) * 4);
            float2 bb = *(float2*)(smem + O_QB + (8 * tb + c2) * 4);
            split2((d[ta][0] + ba.x) * SCALE_Q, (d[ta][1] + ba.y) * SCALE_Q, qh[jj][0], ql[jj][0]);
            split2((d[ta][2] + ba.x) * SCALE_Q, (d[ta][3] + ba.y) * SCALE_Q, qh[jj][1], ql[jj][1]);
            split2((d[tb][0] + bb.x) * SCALE_Q, (d[tb][1] + bb.y) * SCALE_Q, qh[jj][2], ql[jj][2]);
            split2((d[tb][2] + bb.x) * SCALE_Q, (d[tb][3] + bb.y) * SCALE_Q, qh[jj][3], ql[jj][3]);
        }
    }
    __syncthreads();

    // ---- GEMM1b: K ----
    stage_w(qkv_w + 96 * 96, smem, tid);
    __syncthreads();
    {
        float d[12][4];
        #pragma unroll
        for (int j = 0; j < 12; j++) { d[j][0]=0.f; d[j][1]=0.f; d[j][2]=0.f; d[j][3]=0.f; }
        gemm_ss(sb, O_X, O_W, 16 * w, lane, d);
        #pragma unroll
        for (int j = 0; j < 12; j++) {
            float2 bk = *(float2*)(smem + O_QB + (96 + 8 * j + c2) * 4);
            uint32_t h01, l01, h23, l23;
            split2(d[j][0] + bk.x, d[j][1] + bk.y, h01, l01);
            split2(d[j][2] + bk.x, d[j][3] + bk.y, h23, l23);
            uint32_t o0 = (uint32_t)(r0 * XS + 8 * j + c2) << 1;
            uint32_t o1 = (uint32_t)((r0 + 8) * XS + 8 * j + c2) << 1;
            *(uint32_t*)(smem + O_K + o0) = h01;
            *(uint32_t*)(smem + O_K + KLO + o0) = l01;
            *(uint32_t*)(smem + O_K + o1) = h23;
            *(uint32_t*)(smem + O_K + KLO + o1) = l23;
        }
    }
    __syncthreads();

    // ---- GEMM1c: V ----
    stage_w(qkv_w + 192 * 96, smem, tid);
    __syncthreads();
    float dv[12][4];
    {
        #pragma unroll
        for (int j = 0; j < 12; j++) { dv[j][0]=0.f; dv[j][1]=0.f; dv[j][2]=0.f; dv[j][3]=0.f; }
        gemm_ss(sb, O_X, O_W, 16 * w, lane, dv);
        #pragma unroll
        for (int j = 0; j < 12; j++) {
            float2 bv = *(float2*)(smem + O_QB + (192 + 8 * j + c2) * 4);
            dv[j][0] += bv.x; dv[j][1] += bv.y; dv[j][2] += bv.x; dv[j][3] += bv.y;
            int ca = 8 * j + c2, cb = ca + 1;
            #pragma unroll
            for (int h = 0; h < 2; h++) {
                int rr = r0 + 8 * h;
                float va = dv[j][2*h], vb = dv[j][2*h+1];
                __nv_bfloat16 ha = __float2bfloat16(va), hb = __float2bfloat16(vb);
                *(__nv_bfloat16*)(smem + O_VT + ((ca * VS + rr) << 1)) = ha;
                *(__nv_bfloat16*)(smem + O_VT + ((cb * VS + rr) << 1)) = hb;
                *(__nv_bfloat16*)(smem + O_VT + VTLO + ((ca * VS + rr) << 1)) =
                    __float2bfloat16(va - __bfloat162float(ha));
                *(__nv_bfloat16*)(smem + O_VT + VTLO + ((cb * VS + rr) << 1)) =
                    __float2bfloat16(vb - __bfloat162float(hb));
            }
        }
    }
    __syncthreads();   // X region (bf16 X) dead; W region (Wv) dead

    // ---- store v fp32 into X region; stage Wout ----
    #pragma unroll
    for (int j = 0; j < 12; j++) {
        float2 a = { dv[j][0], dv[j][1] }, b = { dv[j][2], dv[j][3] };
        *(float2*)(smem + O_X + ((r0 * FS + 8 * j + c2) << 2)) = a;
        *(float2*)(smem + O_X + (((r0 + 8) * FS + 8 * j + c2) << 2)) = b;
    }
    stage_w(out_w, smem, tid);
    __syncthreads();

    // ---- scores S = Q'K^T (8 n-tiles over this window's 64 tokens) ----
    float s[8][4];
    #pragma unroll
    for (int j = 0; j < 8; j++) { s[j][0]=0.f; s[j][1]=0.f; s[j][2]=0.f; s[j][3]=0.f; }
    #pragma unroll
    for (int k = 0; k < 6; k++) {
        #pragma unroll
        for (int np = 0; np < 4; np++) {
            uint32_t bh[4], bl[4];
            uint32_t baddr = sb + O_K + (((win * 64 + np * 16 + lr) * XS + k * 16 + lc * 8) << 1);
            ldm4(baddr, bh);
            ldm4(baddr + KLO, bl);
            MMA4(s[2*np],   qh[k], bh[0], bh[2]);
            MMA4(s[2*np+1], qh[k], bh[1], bh[3]);
            MMA4(s[2*np],   qh[k], bl[0], bl[2]);
            MMA4(s[2*np+1], qh[k], bl[1], bl[3]);
            MMA4(s[2*np],   ql[k], bh[0], bh[2]);
            MMA4(s[2*np+1], ql[k], bh[1], bh[3]);
        }
    }

    // ---- softmax in registers (row spread over lane quad) ----
    {
        float mx0 = -1e30f, mx1 = -1e30f;
        #pragma unroll
        for (int j = 0; j < 8; j++) {
            mx0 = fmaxf(mx0, fmaxf(s[j][0], s[j][1]));
            mx1 = fmaxf(mx1, fmaxf(s[j][2], s[j][3]));
        }
        mx0 = fmaxf(mx0, __shfl_xor_sync(0xffffffffu, mx0, 1));
        mx0 = fmaxf(mx0, __shfl_xor_sync(0xffffffffu, mx0, 2));
        mx1 = fmaxf(mx1, __shfl_xor_sync(0xffffffffu, mx1, 1));
        mx1 = fmaxf(mx1, __shfl_xor_sync(0xffffffffu, mx1, 2));
        float s0 = 0.f, s1 = 0.f;
        #pragma unroll
        for (int j = 0; j < 8; j++) {
            s[j][0] = __expf(s[j][0] - mx0); s[j][1] = __expf(s[j][1] - mx0);
            s[j][2] = __expf(s[j][2] - mx1); s[j][3] = __expf(s[j][3] - mx1);
            s0 += s[j][0] + s[j][1];
            s1 += s[j][2] + s[j][3];
        }
        s0 += __shfl_xor_sync(0xffffffffu, s0, 1);
        s0 += __shfl_xor_sync(0xffffffffu, s0, 2);
        s1 += __shfl_xor_sync(0xffffffffu, s1, 1);
        s1 += __shfl_xor_sync(0xffffffffu, s1, 2);
        float i0 = 1.0f / s0, i1 = 1.0f / s1;
        #pragma unroll
        for (int j = 0; j < 8; j++) {
            s[j][0] *= i0; s[j][1] *= i0; s[j][2] *= i1; s[j][3] *= i1;
        }
    }
    // repack P -> A-frags (hi/lo)
    uint32_t ph[4][4], pl[4][4];
    #pragma unroll
    for (int jj = 0; jj < 4; jj++) {
        split2(s[2*jj][0],   s[2*jj][1],   ph[jj][0], pl[jj][0]);
        split2(s[2*jj][2],   s[2*jj][3],   ph[jj][1], pl[jj][1]);
        split2(s[2*jj+1][0], s[2*jj+1][1], ph[jj][2], pl[jj][2]);
        split2(s[2*jj+1][2], s[2*jj+1][3], ph[jj][3], pl[jj][3]);
    }

    // ---- PV: O = P @ V  (B = Vt [ch][tok]) ----
    float o[12][4];
    #pragma unroll
    for (int j = 0; j < 12; j++) { o[j][0]=0.f; o[j][1]=0.f; o[j][2]=0.f; o[j][3]=0.f; }
    #pragma unroll
    for (int k = 0; k < 4; k++) {
        #pragma unroll
        for (int np = 0; np < 6; np++) {
            uint32_t bh[4], bl[4];
            uint32_t baddr = sb + O_VT + (((np * 16 + lr) * VS + win * 64 + k * 16 + lc * 8) << 1);
            ldm4(baddr, bh);
            ldm4(baddr + VTLO, bl);
            MMA4(o[2*np],   ph[k], bh[0], bh[2]);
            MMA4(o[2*np+1], ph[k], bh[1], bh[3]);
            MMA4(o[2*np],   ph[k], bl[0], bl[2]);
            MMA4(o[2*np+1], ph[k], bl[1], bl[3]);
            MMA4(o[2*np],   pl[k], bh[0], bh[2]);
            MMA4(o[2*np+1], pl[k], bh[1], bh[3]);
        }
    }

    // ---- O' = O + LePE + conv_b; repack to A-frags ----
    uint32_t oh[6][4], ol[6][4];
    {
        const int rowbase = win * 64;
        #pragma unroll
        for (int j = 0; j < 12; j++) {
            int c0 = 8 * j + c2;
            float2 cb2 = *(float2*)(smem + O_CB + c0 * 4);
            float2 cw2[9];
            #pragma unroll
            for (int tap = 0; tap < 9; tap++)
                cw2[tap] = *(float2*)(smem + O_CW + (tap * 96 + c0) * 4);
            #pragma unroll
            for (int h = 0; h < 2; h++) {
                int row = r0 + 8 * h;
                int tl = row - rowbase, y = tl >> 3, xx = tl & 7;
                float ax = o[j][2*h] + cb2.x, ay = o[j][2*h+1] + cb2.y;
                #pragma unroll
                for (int dy = -1; dy <= 1; dy++) {
                    int yy = y + dy;
                    if ((unsigned)yy > 7u) continue;
                    #pragma unroll
                    for (int dx = -1; dx <= 1; dx++) {
                        int xc = xx + dx;
                        if ((unsigned)xc > 7u) continue;
                        int nb = rowbase + yy * 8 + xc;
                        float2 v2 = *(float2*)(smem + O_X + ((nb * FS + c0) << 2));
                        float2 cw = cw2[(dy + 1) * 3 + (dx + 1)];
                        ax += v2.x * cw.x;
                        ay += v2.y * cw.y;
                    }
                }
                o[j][2*h] = ax; o[j][2*h+1] = ay;
            }
        }
        #pragma unroll
        for (int jj = 0; jj < 6; jj++) {
            split2(o[2*jj][0],   o[2*jj][1],   oh[jj][0], ol[jj][0]);
            split2(o[2*jj][2],   o[2*jj][3],   oh[jj][1], ol[jj][1]);
            split2(o[2*jj+1][0], o[2*jj+1][1], oh[jj][2], ol[jj][2]);
            split2(o[2*jj+1][2], o[2*jj+1][3], oh[jj][3], ol[jj][3]);
        }
    }
    __syncthreads();   // v fp32 dead -> X region becomes outstage

    // ---- GEMM3: out = O' @ out_w^T + out_b -> outstage ----
    {
        float f[12][4];
        #pragma unroll
        for (int j = 0; j < 12; j++) { f[j][0]=0.f; f[j][1]=0.f; f[j][2]=0.f; f[j][3]=0.f; }
        #pragma unroll
        for (int k = 0; k < 6; k++) {
            #pragma unroll
            for (int np = 0; np < 6; np++) {
                uint32_t bh[4], bl[4];
                uint32_t baddr = sb + O_W + (((np * 16 + lr) * XS + k * 16 + lc * 8) << 1);
                ldm4(baddr, bh);
                ldm4(baddr + WLO, bl);
                MMA4(f[2*np],   oh[k], bh[0], bh[2]);
                MMA4(f[2*np+1], oh[k], bh[1], bh[3]);
                MMA4(f[2*np],   oh[k], bl[0], bl[2]);
                MMA4(f[2*np+1], oh[k], bl[1], bl[3]);
                MMA4(f[2*np],   ol[k], bh[0], bh[2]);
                MMA4(f[2*np+1], ol[k], bh[1], bh[3]);
            }
        }
        #pragma unroll
        for (int j = 0; j < 12; j++) {
            float2 bo = *(float2*)(smem + O_OB + (8 * j + c2) * 4);
            float2 a = { f[j][0] + bo.x, f[j][1] + bo.y };
            float2 b = { f[j][2] + bo.x, f[j][3] + bo.y };
            *(float2*)(smem + O_X + ((r0 * FS + 8 * j + c2) << 2)) = a;
            *(float2*)(smem + O_X + (((r0 + 8) * FS + 8 * j + c2) << 2)) = b;
        }
    }
    __syncthreads();

    // ---- coalesced writeout ----
    float* og = out + ((size_t)bI * 96) * 65536 + (size_t)(wh * 8) * 256 + wv0 * 8;
    #pragma unroll
    for (int it = 0; it < 12; it++) {
        int e = it * 256 + tid;
        int c4 = e >> 7, i = (e >> 4) & 7, jj = e & 15;
        int m = ((jj >> 3) << 6) + (i << 3) + (jj & 7);
        const float* st = (const float*)(smem + O_X) + m * FS + c4 * 4;
        float2 u = *(const float2*)st;
        float2 v = *(const float2*)(st + 2);
        float* g = og + (size_t)(c4 * 4) * 65536 + i * 256 + jj;
        g[0] = u.x; g[65536] = u.y; g[131072] = v.x; g[196608] = v.y;
    }
}

extern "C" void kernel_launch(void* const* d_in, const int* in_sizes, int n_in,
                              void* d_out, int out_size) {
    const float* x      = (const float*)d_in[0];
    const float* qkv_w  = (const float*)d_in[1];
    const float* qkv_b  = (const float*)d_in[2];
    const float* conv_w = (const float*)d_in[3];
    const float* conv_b = (const float*)d_in[4];
    const float* out_w  = (const float*)d_in[5];
    const float* out_b  = (const float*)d_in[6];
    float* out = (float*)d_out;

    cudaFuncSetAttribute(vitblock_mma,
                         cudaFuncAttributeMaxDynamicSharedMemorySize, SMEM_BYTES);
    vitblock_mma<<<4096, 256, SMEM_BYTES>>>(x, qkv_w, qkv_b, conv_w, conv_b,
                                            out_w, out_b, out);
}

// round 4
// speedup vs baseline: 2.5920x; 1.0809x over previous
#include <cuda_runtime.h>
#include <cuda_bf16.h>
#include <cstdint>

#define SCALE_Q 0.10206207261596575f   // 1/sqrt(96)
#define XS 104   // bf16 row stride for 96-col operand tiles
#define VS 136   // Vt row stride (tok dim 128 + 8)
#define FS 98    // fp32 staging stride

// ---- smem byte offsets ----
#define O_QB   0          // qkv_b 288 f
#define O_CW   1152       // cwT[9][96] 864 f
#define O_CB   4608       // conv_b 96 f
#define O_OB   4992       // out_b 96 f
#define O_X    5376       // X hi/lo bf16 [128][104]x2; later v fp32 [128][98]; later outstage
#define XLO    26624
#define O_W    58624      // W chunk hi/lo [96][104]x2 = 39936
#define WLO    19968
#define O_K    98560      // K hi/lo [128][104]x2 = 53248
#define KLO    26624
#define O_VT   151808     // Vt hi/lo [96][136]x2 = 52224
#define VTLO   26112
#define SMEM_BYTES 204032

#define WCHUNK_BYTES 39936
__device__ __align__(16) unsigned char g_wc[4][WCHUNK_BYTES];  // Q,K,V,OUT converted

__device__ __forceinline__ uint32_t smem_u32(const void* p) {
    uint32_t a;
    asm("{ .reg .u64 t; cvta.to.shared.u64 t, %1; cvt.u32.u64 %0, t; }" : "=r"(a) : "l"(p));
    return a;
}
__device__ __forceinline__ void ldm4(uint32_t a, uint32_t* r) {
    asm volatile("ldmatrix.sync.aligned.m8n8.x4.shared.b16 {%0,%1,%2,%3}, [%4];"
                 : "=r"(r[0]), "=r"(r[1]), "=r"(r[2]), "=r"(r[3]) : "r"(a));
}
#define MMA4(D, A, B0, B1) \
    asm volatile("mma.sync.aligned.m16n8k16.row.col.f32.bf16.bf16.f32 " \
        "{%0,%1,%2,%3},{%4,%5,%6,%7},{%8,%9},{%0,%1,%2,%3};" \
        : "+f"((D)[0]), "+f"((D)[1]), "+f"((D)[2]), "+f"((D)[3]) \
        : "r"((A)[0]), "r"((A)[1]), "r"((A)[2]), "r"((A)[3]), "r"(B0), "r"(B1))

__device__ __forceinline__ void cp16(uint32_t s, const void* g) {
    asm volatile("{ .reg .u64 gg; cvta.to.global.u64 gg, %1;\n\t"
                 "cp.async.cg.shared.global [%0], [gg], 16; }"
                 :: "r"(s), "l"(g) : "memory");
}
#define CP_COMMIT() asm volatile("cp.async.commit_group;" ::: "memory")
#define CP_WAIT0()  asm volatile("cp.async.wait_group 0;" ::: "memory")

__device__ __forceinline__ uint32_t bpack(__nv_bfloat16 a, __nv_bfloat16 b) {
    __nv_bfloat162 t = __halves2bfloat162(a, b);
    return *reinterpret_cast<uint32_t*>(&t);
}
__device__ __forceinline__ void split2(float a, float b, uint32_t& h, uint32_t& l) {
    __nv_bfloat16 ha = __float2bfloat16(a), hb = __float2bfloat16(b);
    h = bpack(ha, hb);
    l = bpack(__float2bfloat16(a - __bfloat162float(ha)),
              __float2bfloat16(b - __bfloat162float(hb)));
}

// ---- prep: convert weights to hi/lo bf16 byte-image of the smem W layout ----
__global__ void prep_w(const float* __restrict__ qkv_w, const float* __restrict__ out_w) {
    int e = blockIdx.x * 256 + threadIdx.x;
    if (e >= 4 * 2304) return;
    int chunk = e / 2304, r = e - chunk * 2304;
    int o = r / 24, q = r - o * 24;
    const float* src = (chunk < 3 ? qkv_w + chunk * 96 * 96 : out_w) + o * 96 + q * 4;
    float4 v = *(const float4*)src;
    __nv_bfloat16 h0 = __float2bfloat16(v.x), h1 = __float2bfloat16(v.y);
    __nv_bfloat16 h2 = __float2bfloat16(v.z), h3 = __float2bfloat16(v.w);
    uint2 H = { bpack(h0, h1), bpack(h2, h3) };
    uint2 L = { bpack(__float2bfloat16(v.x - __bfloat162float(h0)),
                      __float2bfloat16(v.y - __bfloat162float(h1))),
                bpack(__float2bfloat16(v.z - __bfloat162float(h2)),
                      __float2bfloat16(v.w - __bfloat162float(h3))) };
    uint32_t off = (uint32_t)(o * XS + q * 4) << 1;
    *(uint2*)(g_wc[chunk] + off) = H;
    *(uint2*)(g_wc[chunk] + WLO + off) = L;
}

// async-stage one converted weight chunk into O_W
__device__ __forceinline__ void stage_w_async(uint32_t sb, int chunk, int tid) {
    const unsigned char* g = g_wc[chunk];
    #pragma unroll
    for (int i = 0; i < 10; i++) {
        int e = i * 256 + tid;
        if (e < WCHUNK_BYTES / 16) cp16(sb + O_W + e * 16, g + e * 16);
    }
    CP_COMMIT();
}

// 4Mx2N-tiled GEMM: warp (mw,nw) computes rows [mw*32,+32), cols [nw*48,+48)
__device__ __forceinline__ void gemm42(uint32_t sb, int mw, int nw, int lane,
                                       float d[2][6][4]) {
    const int lr = lane & 15, lc = lane >> 4;
    #pragma unroll
    for (int k = 0; k < 6; k++) {
        uint32_t ah[2][4], al[2][4];
        #pragma unroll
        for (int mi = 0; mi < 2; mi++) {
            uint32_t aa = sb + O_X + (((mw * 32 + mi * 16 + lr) * XS + k * 16 + lc * 8) << 1);
            ldm4(aa, ah[mi]);
            ldm4(aa + XLO, al[mi]);
        }
        #pragma unroll
        for (int ni = 0; ni < 3; ni++) {
            uint32_t bh[4], bl[4];
            uint32_t ba = sb + O_W + (((nw * 48 + ni * 16 + lr) * XS + k * 16 + lc * 8) << 1);
            ldm4(ba, bh);
            ldm4(ba + WLO, bl);
            #pragma unroll
            for (int mi = 0; mi < 2; mi++) {
                MMA4(d[mi][2*ni],   ah[mi], bh[0], bh[2]);
                MMA4(d[mi][2*ni+1], ah[mi], bh[1], bh[3]);
                MMA4(d[mi][2*ni],   ah[mi], bl[0], bl[2]);
                MMA4(d[mi][2*ni+1], ah[mi], bl[1], bl[3]);
                MMA4(d[mi][2*ni],   al[mi], bh[0], bh[2]);
                MMA4(d[mi][2*ni+1], al[mi], bh[1], bh[3]);
            }
        }
    }
}

__global__ __launch_bounds__(256, 1)
void vitblock_mma(const float* __restrict__ x,
                  const float* __restrict__ qkv_b,
                  const float* __restrict__ conv_w,
                  const float* __restrict__ conv_b,
                  const float* __restrict__ out_b,
                  float* __restrict__ out)
{
    extern __shared__ char smem[];
    const uint32_t sb = smem_u32(smem);
    const int tid = threadIdx.x;
    const int w = tid >> 5, lane = tid & 31;
    const int lr = lane & 15, lc = lane >> 4;
    const int c2 = (lane & 3) * 2;
    const int r0 = 16 * w + (lane >> 2);
    const int win = w >> 2;
    const int mw = w >> 1, nw = w & 1;     // 4x2 warp tiling

    const int wv0 = (blockIdx.x << 1) & 31;
    const int wh  = (blockIdx.x >> 4) & 31;
    const int bI  = blockIdx.x >> 9;
    const float* xg = x + ((size_t)bI * 96) * 65536 + (size_t)(wh * 8) * 256 + wv0 * 8;

    // ---- P0: async Wk, stage consts + X ----
    stage_w_async(sb, 1, tid);   // K weights first
    for (int i = tid; i < 288; i += 256) *(float*)(smem + O_QB + i * 4) = qkv_b[i];
    for (int i = tid; i < 864; i += 256) {
        int ch = i / 9, tap = i - ch * 9;
        *(float*)(smem + O_CW + (tap * 96 + ch) * 4) = conv_w[i];
    }
    if (tid < 96) {
        *(float*)(smem + O_CB + tid * 4) = conv_b[tid];
        *(float*)(smem + O_OB + tid * 4) = out_b[tid];
    }
    #pragma unroll
    for (int it = 0; it < 12; it++) {
        int e = it * 256 + tid;                  // 3072 = 24 c4 x 8 i x 16 jj
        int c4 = e >> 7, i = (e >> 4) & 7, jj = e & 15;
        const float* p = xg + (size_t)(c4 * 4) * 65536 + i * 256 + jj;
        float v0 = p[0], v1 = p[65536], v2 = p[131072], v3 = p[196608];
        int m = ((jj >> 3) << 6) + (i << 3) + (jj & 7);
        __nv_bfloat16 h0 = __float2bfloat16(v0), h1 = __float2bfloat16(v1);
        __nv_bfloat16 h2 = __float2bfloat16(v2), h3 = __float2bfloat16(v3);
        uint2 H = { bpack(h0, h1), bpack(h2, h3) };
        uint2 L = { bpack(__float2bfloat16(v0 - __bfloat162float(h0)),
                          __float2bfloat16(v1 - __bfloat162float(h1))),
                    bpack(__float2bfloat16(v2 - __bfloat162float(h2)),
                          __float2bfloat16(v3 - __bfloat162float(h3))) };
        uint32_t off = (uint32_t)(m * XS + c4 * 4) << 1;
        *(uint2*)(smem + O_X + off) = H;
        *(uint2*)(smem + O_X + XLO + off) = L;
    }
    CP_WAIT0();
    __syncthreads();

    // ---- GEMM K (4x2 tiling) ----
    {
        float d[2][6][4];
        #pragma unroll
        for (int a = 0; a < 2; a++)
            #pragma unroll
            for (int j = 0; j < 6; j++) { d[a][j][0]=0.f; d[a][j][1]=0.f; d[a][j][2]=0.f; d[a][j][3]=0.f; }
        gemm42(sb, mw, nw, lane, d);
        __syncthreads();              // all warps done reading Wk
        stage_w_async(sb, 0, tid);    // prefetch Wq (overlaps K store)
        #pragma unroll
        for (int mi = 0; mi < 2; mi++)
            #pragma unroll
            for (int j = 0; j < 6; j++) {
                int col = nw * 48 + 8 * j + c2;
                float2 bk = *(float2*)(smem + O_QB + (96 + col) * 4);
                #pragma unroll
                for (int h = 0; h < 2; h++) {
                    int row = mw * 32 + mi * 16 + (lane >> 2) + 8 * h;
                    uint32_t hh, ll;
                    split2(d[mi][j][2*h] + bk.x, d[mi][j][2*h+1] + bk.y, hh, ll);
                    uint32_t o0 = (uint32_t)(row * XS + col) << 1;
                    *(uint32_t*)(smem + O_K + o0) = hh;
                    *(uint32_t*)(smem + O_K + KLO + o0) = ll;
                }
            }
        CP_WAIT0();
        __syncthreads();
    }

    // ---- GEMM Q (M-only; keep fragments in regs) ----
    uint32_t qh[6][4], ql[6][4];
    {
        float d[12][4];
        #pragma unroll
        for (int j = 0; j < 12; j++) { d[j][0]=0.f; d[j][1]=0.f; d[j][2]=0.f; d[j][3]=0.f; }
        #pragma unroll
        for (int k = 0; k < 6; k++) {
            uint32_t ah[4], al[4];
            uint32_t aa = sb + O_X + (((16 * w + lr) * XS + k * 16 + lc * 8) << 1);
            ldm4(aa, ah);
            ldm4(aa + XLO, al);
            #pragma unroll
            for (int np = 0; np < 6; np++) {
                uint32_t bh[4], bl[4];
                uint32_t ba = sb + O_W + (((np * 16 + lr) * XS + k * 16 + lc * 8) << 1);
                ldm4(ba, bh);
                ldm4(ba + WLO, bl);
                MMA4(d[2*np],   ah, bh[0], bh[2]);
                MMA4(d[2*np+1], ah, bh[1], bh[3]);
                MMA4(d[2*np],   ah, bl[0], bl[2]);
                MMA4(d[2*np+1], ah, bl[1], bl[3]);
                MMA4(d[2*np],   al, bh[0], bh[2]);
                MMA4(d[2*np+1], al, bh[1], bh[3]);
            }
        }
        __syncthreads();              // done reading Wq
        stage_w_async(sb, 2, tid);    // prefetch Wv (overlaps Q conversion)
        #pragma unroll
        for (int jj = 0; jj < 6; jj++) {
            int ta = 2 * jj, tb = 2 * jj + 1;
            float2 ba = *(float2*)(smem + O_QB + (8 * ta + c2) * 4);
            float2 bb = *(float2*)(smem + O_QB + (8 * tb + c2) * 4);
            split2((d[ta][0] + ba.x) * SCALE_Q, (d[ta][1] + ba.y) * SCALE_Q, qh[jj][0], ql[jj][0]);
            split2((d[ta][2] + ba.x) * SCALE_Q, (d[ta][3] + ba.y) * SCALE_Q, qh[jj][1], ql[jj][1]);
            split2((d[tb][0] + bb.x) * SCALE_Q, (d[tb][1] + bb.y) * SCALE_Q, qh[jj][2], ql[jj][2]);
            split2((d[tb][2] + bb.x) * SCALE_Q, (d[tb][3] + bb.y) * SCALE_Q, qh[jj][3], ql[jj][3]);
        }
        CP_WAIT0();
        __syncthreads();
    }

    // ---- GEMM V (4x2 tiling) ----
    {
        float d[2][6][4];
        #pragma unroll
        for (int a = 0; a < 2; a++)
            #pragma unroll
            for (int j = 0; j < 6; j++) { d[a][j][0]=0.f; d[a][j][1]=0.f; d[a][j][2]=0.f; d[a][j][3]=0.f; }
        gemm42(sb, mw, nw, lane, d);
        __syncthreads();              // done reading Wv AND X (X becomes v fp32)
        stage_w_async(sb, 3, tid);    // prefetch Wout (overlaps everything to GEMM3)
        #pragma unroll
        for (int mi = 0; mi < 2; mi++)
            #pragma unroll
            for (int j = 0; j < 6; j++) {
                int ca = nw * 48 + 8 * j + c2, cb = ca + 1;
                float2 bv = *(float2*)(smem + O_QB + (192 + ca) * 4);
                #pragma unroll
                for (int h = 0; h < 2; h++) {
                    int row = mw * 32 + mi * 16 + (lane >> 2) + 8 * h;
                    float va = d[mi][j][2*h] + bv.x, vb = d[mi][j][2*h+1] + bv.y;
                    // v fp32 (for LePE) into X region
                    float2 vf = { va, vb };
                    *(float2*)(smem + O_X + ((row * FS + ca) << 2)) = vf;
                    // vT hi/lo bf16 (for PV)
                    __nv_bfloat16 ha = __float2bfloat16(va), hb = __float2bfloat16(vb);
                    *(__nv_bfloat16*)(smem + O_VT + ((ca * VS + row) << 1)) = ha;
                    *(__nv_bfloat16*)(smem + O_VT + ((cb * VS + row) << 1)) = hb;
                    *(__nv_bfloat16*)(smem + O_VT + VTLO + ((ca * VS + row) << 1)) =
                        __float2bfloat16(va - __bfloat162float(ha));
                    *(__nv_bfloat16*)(smem + O_VT + VTLO + ((cb * VS + row) << 1)) =
                        __float2bfloat16(vb - __bfloat162float(hb));
                }
            }
        __syncthreads();
    }

    // ---- scores S = Q'K^T ----
    float s[8][4];
    #pragma unroll
    for (int j = 0; j < 8; j++) { s[j][0]=0.f; s[j][1]=0.f; s[j][2]=0.f; s[j][3]=0.f; }
    #pragma unroll
    for (int k = 0; k < 6; k++) {
        #pragma unroll
        for (int np = 0; np < 4; np++) {
            uint32_t bh[4], bl[4];
            uint32_t baddr = sb + O_K + (((win * 64 + np * 16 + lr) * XS + k * 16 + lc * 8) << 1);
            ldm4(baddr, bh);
            ldm4(baddr + KLO, bl);
            MMA4(s[2*np],   qh[k], bh[0], bh[2]);
            MMA4(s[2*np+1], qh[k], bh[1], bh[3]);
            MMA4(s[2*np],   qh[k], bl[0], bl[2]);
            MMA4(s[2*np+1], qh[k], bl[1], bl[3]);
            MMA4(s[2*np],   ql[k], bh[0], bh[2]);
            MMA4(s[2*np+1], ql[k], bh[1], bh[3]);
        }
    }

    // ---- softmax in registers ----
    {
        float mx0 = -1e30f, mx1 = -1e30f;
        #pragma unroll
        for (int j = 0; j < 8; j++) {
            mx0 = fmaxf(mx0, fmaxf(s[j][0], s[j][1]));
            mx1 = fmaxf(mx1, fmaxf(s[j][2], s[j][3]));
        }
        mx0 = fmaxf(mx0, __shfl_xor_sync(0xffffffffu, mx0, 1));
        mx0 = fmaxf(mx0, __shfl_xor_sync(0xffffffffu, mx0, 2));
        mx1 = fmaxf(mx1, __shfl_xor_sync(0xffffffffu, mx1, 1));
        mx1 = fmaxf(mx1, __shfl_xor_sync(0xffffffffu, mx1, 2));
        float s0 = 0.f, s1 = 0.f;
        #pragma unroll
        for (int j = 0; j < 8; j++) {
            s[j][0] = __expf(s[j][0] - mx0); s[j][1] = __expf(s[j][1] - mx0);
            s[j][2] = __expf(s[j][2] - mx1); s[j][3] = __expf(s[j][3] - mx1);
            s0 += s[j][0] + s[j][1];
            s1 += s[j][2] + s[j][3];
        }
        s0 += __shfl_xor_sync(0xffffffffu, s0, 1);
        s0 += __shfl_xor_sync(0xffffffffu, s0, 2);
        s1 += __shfl_xor_sync(0xffffffffu, s1, 1);
        s1 += __shfl_xor_sync(0xffffffffu, s1, 2);
        float i0 = 1.0f / s0, i1 = 1.0f / s1;
        #pragma unroll
        for (int j = 0; j < 8; j++) {
            s[j][0] *= i0; s[j][1] *= i0; s[j][2] *= i1; s[j][3] *= i1;
        }
    }
    uint32_t ph[4][4], pl[4][4];
    #pragma unroll
    for (int jj = 0; jj < 4; jj++) {
        split2(s[2*jj][0],   s[2*jj][1],   ph[jj][0], pl[jj][0]);
        split2(s[2*jj][2],   s[2*jj][3],   ph[jj][1], pl[jj][1]);
        split2(s[2*jj+1][0], s[2*jj+1][1], ph[jj][2], pl[jj][2]);
        split2(s[2*jj+1][2], s[2*jj+1][3], ph[jj][3], pl[jj][3]);
    }

    // ---- PV: O = P @ V ----
    float o[12][4];
    #pragma unroll
    for (int j = 0; j < 12; j++) { o[j][0]=0.f; o[j][1]=0.f; o[j][2]=0.f; o[j][3]=0.f; }
    #pragma unroll
    for (int k = 0; k < 4; k++) {
        #pragma unroll
        for (int np = 0; np < 6; np++) {
            uint32_t bh[4], bl[4];
            uint32_t baddr = sb + O_VT + (((np * 16 + lr) * VS + win * 64 + k * 16 + lc * 8) << 1);
            ldm4(baddr, bh);
            ldm4(baddr + VTLO, bl);
            MMA4(o[2*np],   ph[k], bh[0], bh[2]);
            MMA4(o[2*np+1], ph[k], bh[1], bh[3]);
            MMA4(o[2*np],   ph[k], bl[0], bl[2]);
            MMA4(o[2*np+1], ph[k], bl[1], bl[3]);
            MMA4(o[2*np],   pl[k], bh[0], bh[2]);
            MMA4(o[2*np+1], pl[k], bh[1], bh[3]);
        }
    }

    // ---- O' = O + LePE + conv_b; repack to A-frags ----
    uint32_t oh[6][4], ol[6][4];
    {
        const int rowbase = win * 64;
        #pragma unroll
        for (int j = 0; j < 12; j++) {
            int c0 = 8 * j + c2;
            float2 cb2 = *(float2*)(smem + O_CB + c0 * 4);
            float2 cw2[9];
            #pragma unroll
            for (int tap = 0; tap < 9; tap++)
                cw2[tap] = *(float2*)(smem + O_CW + (tap * 96 + c0) * 4);
            #pragma unroll
            for (int h = 0; h < 2; h++) {
                int row = r0 + 8 * h;
                int tl = row - rowbase, y = tl >> 3, xx = tl & 7;
                float ax = o[j][2*h] + cb2.x, ay = o[j][2*h+1] + cb2.y;
                #pragma unroll
                for (int dy = -1; dy <= 1; dy++) {
                    int yy = y + dy;
                    if ((unsigned)yy > 7u) continue;
                    #pragma unroll
                    for (int dx = -1; dx <= 1; dx++) {
                        int xc = xx + dx;
                        if ((unsigned)xc > 7u) continue;
                        int nb = rowbase + yy * 8 + xc;
                        float2 v2 = *(float2*)(smem + O_X + ((nb * FS + c0) << 2));
                        float2 cw = cw2[(dy + 1) * 3 + (dx + 1)];
                        ax += v2.x * cw.x;
                        ay += v2.y * cw.y;
                    }
                }
                o[j][2*h] = ax; o[j][2*h+1] = ay;
            }
        }
        #pragma unroll
        for (int jj = 0; jj < 6; jj++) {
            split2(o[2*jj][0],   o[2*jj][1],   oh[jj][0], ol[jj][0]);
            split2(o[2*jj][2],   o[2*jj][3],   oh[jj][1], ol[jj][1]);
            split2(o[2*jj+1][0], o[2*jj+1][1], oh[jj][2], ol[jj][2]);
            split2(o[2*jj+1][2], o[2*jj+1][3], oh[jj][3], ol[jj][3]);
        }
    }
    CP_WAIT0();          // Wout landed long ago
    __syncthreads();     // v fp32 dead -> X region becomes outstage

    // ---- GEMM3: out = O' @ out_w^T + out_b ----
    {
        float f[12][4];
        #pragma unroll
        for (int j = 0; j < 12; j++) { f[j][0]=0.f; f[j][1]=0.f; f[j][2]=0.f; f[j][3]=0.f; }
        #pragma unroll
        for (int k = 0; k < 6; k++) {
            #pragma unroll
            for (int np = 0; np < 6; np++) {
                uint32_t bh[4], bl[4];
                uint32_t baddr = sb + O_W + (((np * 16 + lr) * XS + k * 16 + lc * 8) << 1);
                ldm4(baddr, bh);
                ldm4(baddr + WLO, bl);
                MMA4(f[2*np],   oh[k], bh[0], bh[2]);
                MMA4(f[2*np+1], oh[k], bh[1], bh[3]);
                MMA4(f[2*np],   oh[k], bl[0], bl[2]);
                MMA4(f[2*np+1], oh[k], bl[1], bl[3]);
                MMA4(f[2*np],   ol[k], bh[0], bh[2]);
                MMA4(f[2*np+1], ol[k], bh[1], bh[3]);
            }
        }
        #pragma unroll
        for (int j = 0; j < 12; j++) {
            float2 bo = *(float2*)(smem + O_OB + (8 * j + c2) * 4);
            float2 a = { f[j][0] + bo.x, f[j][1] + bo.y };
            float2 b = { f[j][2] + bo.x, f[j][3] + bo.y };
            *(float2*)(smem + O_X + ((r0 * FS + 8 * j + c2) << 2)) = a;
            *(float2*)(smem + O_X + (((r0 + 8) * FS + 8 * j + c2) << 2)) = b;
        }
    }
    __syncthreads();

    // ---- coalesced writeout ----
    float* og = out + ((size_t)bI * 96) * 65536 + (size_t)(wh * 8) * 256 + wv0 * 8;
    #pragma unroll
    for (int it = 0; it < 12; it++) {
        int e = it * 256 + tid;
        int c4 = e >> 7, i = (e >> 4) & 7, jj = e & 15;
        int m = ((jj >> 3) << 6) + (i << 3) + (jj & 7);
        const float* st = (const float*)(smem + O_X) + m * FS + c4 * 4;
        float2 u = *(const float2*)st;
        float2 v = *(const float2*)(st + 2);
        float* g = og + (size_t)(c4 * 4) * 65536 + i * 256 + jj;
        g[0] = u.x; g[65536] = u.y; g[131072] = v.x; g[196608] = v.y;
    }
}

extern "C" void kernel_launch(void* const* d_in, const int* in_sizes, int n_in,
                              void* d_out, int out_size) {
    const float* x      = (const float*)d_in[0];
    const float* qkv_w  = (const float*)d_in[1];
    const float* qkv_b  = (const float*)d_in[2];
    const float* conv_w = (const float*)d_in[3];
    const float* conv_b = (const float*)d_in[4];
    const float* out_w  = (const float*)d_in[5];
    const float* out_b  = (const float*)d_in[6];
    float* out = (float*)d_out;

    prep_w<<<36, 256>>>(qkv_w, out_w);
    cudaFuncSetAttribute(vitblock_mma,
                         cudaFuncAttributeMaxDynamicSharedMemorySize, SMEM_BYTES);
    vitblock_mma<<<4096, 256, SMEM_BYTES>>>(x, qkv_b, conv_w, conv_b, out_b, out);
}

// round 5
// speedup vs baseline: 2.7034x; 1.0430x over previous
#include <cuda_runtime.h>
#include <cuda_bf16.h>
#include <cstdint>

#define SCALE_Q 0.10206207261596575f   // 1/sqrt(96)
#define XS 104   // bf16 row stride (96 cols + 8 pad) -> conflict-free ldmatrix
#define FS 98    // fp32 staging stride

// ---- smem byte offsets (total 105216 -> 2 CTAs/SM) ----
#define O_QB 0          // qkv_b 288 f
#define O_CW 1152       // cwT[9][96]
#define O_CB 4608
#define O_OB 4992
#define O_X  5376       // X hi/lo [64][104]x2 = 26624; later v fp32 [64][98]; later outstage
#define XLO2 13312
#define O_W  32000      // W half-chunk hi/lo [48][104]x2 = 19968
#define WLO2 9984
#define O_K  51968      // K hi/lo [64][104]x2 = 26624
#define KLO2 13312
#define O_V  78592      // V hi/lo [64][104]x2 = 26624 (tok-major; PV uses ldmatrix.trans)
#define VLO2 13312
#define SMEM_BYTES 105216

#define WHALF_BYTES 19968
__device__ __align__(16) unsigned char g_wc[4][2][WHALF_BYTES];  // Q,K,V,OUT x 2 halves

__device__ __forceinline__ uint32_t smem_u32(const void* p) {
    uint32_t a;
    asm("{ .reg .u64 t; cvta.to.shared.u64 t, %1; cvt.u32.u64 %0, t; }" : "=r"(a) : "l"(p));
    return a;
}
__device__ __forceinline__ void ldm4(uint32_t a, uint32_t* r) {
    asm volatile("ldmatrix.sync.aligned.m8n8.x4.shared.b16 {%0,%1,%2,%3}, [%4];"
                 : "=r"(r[0]), "=r"(r[1]), "=r"(r[2]), "=r"(r[3]) : "r"(a));
}
__device__ __forceinline__ void ldm4t(uint32_t a, uint32_t* r) {
    asm volatile("ldmatrix.sync.aligned.m8n8.x4.trans.shared.b16 {%0,%1,%2,%3}, [%4];"
                 : "=r"(r[0]), "=r"(r[1]), "=r"(r[2]), "=r"(r[3]) : "r"(a));
}
#define MMA4(D, A, B0, B1) \
    asm volatile("mma.sync.aligned.m16n8k16.row.col.f32.bf16.bf16.f32 " \
        "{%0,%1,%2,%3},{%4,%5,%6,%7},{%8,%9},{%0,%1,%2,%3};" \
        : "+f"((D)[0]), "+f"((D)[1]), "+f"((D)[2]), "+f"((D)[3]) \
        : "r"((A)[0]), "r"((A)[1]), "r"((A)[2]), "r"((A)[3]), "r"(B0), "r"(B1))

__device__ __forceinline__ void cp16(uint32_t s, const void* g) {
    asm volatile("{ .reg .u64 gg; cvta.to.global.u64 gg, %1;\n\t"
                 "cp.async.cg.shared.global [%0], [gg], 16; }"
                 :: "r"(s), "l"(g) : "memory");
}
#define CP_COMMIT() asm volatile("cp.async.commit_group;" ::: "memory")
#define CP_WAIT0()  asm volatile("cp.async.wait_group 0;" ::: "memory")

__device__ __forceinline__ uint32_t bpack(__nv_bfloat16 a, __nv_bfloat16 b) {
    __nv_bfloat162 t = __halves2bfloat162(a, b);
    return *reinterpret_cast<uint32_t*>(&t);
}
__device__ __forceinline__ void split2(float a, float b, uint32_t& h, uint32_t& l) {
    __nv_bfloat16 ha = __float2bfloat16(a), hb = __float2bfloat16(b);
    h = bpack(ha, hb);
    l = bpack(__float2bfloat16(a - __bfloat162float(ha)),
              __float2bfloat16(b - __bfloat162float(hb)));
}

// ---- prep: convert weights to hi/lo bf16 half-chunk images ----
__global__ void prep_w(const float* __restrict__ qkv_w, const float* __restrict__ out_w) {
    int e = blockIdx.x * 256 + threadIdx.x;
    if (e >= 4 * 2304) return;
    int chunk = e / 2304, r = e - chunk * 2304;
    int o = r / 24, q = r - o * 24;
    const float* src = (chunk < 3 ? qkv_w + chunk * 9216 : out_w) + o * 96 + q * 4;
    float4 v = *(const float4*)src;
    __nv_bfloat16 h0 = __float2bfloat16(v.x), h1 = __float2bfloat16(v.y);
    __nv_bfloat16 h2 = __float2bfloat16(v.z), h3 = __float2bfloat16(v.w);
    uint2 H = { bpack(h0, h1), bpack(h2, h3) };
    uint2 L = { bpack(__float2bfloat16(v.x - __bfloat162float(h0)),
                      __float2bfloat16(v.y - __bfloat162float(h1))),
                bpack(__float2bfloat16(v.z - __bfloat162float(h2)),
                      __float2bfloat16(v.w - __bfloat162float(h3))) };
    int half = o / 48, lr = o - half * 48;
    uint32_t off = (uint32_t)(lr * XS + q * 4) << 1;
    *(uint2*)(g_wc[chunk][half] + off) = H;
    *(uint2*)(g_wc[chunk][half] + WLO2 + off) = L;
}

__device__ __forceinline__ void stage_half(uint32_t sb, int chunk, int h, int tid) {
    const unsigned char* g = g_wc[chunk][h];
    #pragma unroll
    for (int i = 0; i < 10; i++) {
        int e = i * 128 + tid;
        if (e < WHALF_BYTES / 16) cp16(sb + O_W + e * 16, g + e * 16);
    }
    CP_COMMIT();
}

// one 48-col half of a projection GEMM: warp w does rows [16w,16w+16)
__device__ __forceinline__ void gemm_half(uint32_t sb, int h, int w, int lane,
                                          float d[12][4]) {
    const int lr = lane & 15, lc = lane >> 4;
    #pragma unroll
    for (int k = 0; k < 6; k++) {
        uint32_t ah[4], al[4];
        uint32_t aa = sb + O_X + (((w * 16 + lr) * XS + k * 16 + lc * 8) << 1);
        ldm4(aa, ah);
        ldm4(aa + XLO2, al);
        #pragma unroll
        for (int ni = 0; ni < 3; ni++) {
            uint32_t bh[4], bl[4];
            uint32_t ba = sb + O_W + (((ni * 16 + lr) * XS + k * 16 + lc * 8) << 1);
            ldm4(ba, bh);
            ldm4(ba + WLO2, bl);
            int j = h * 6 + 2 * ni;
            MMA4(d[j],   ah, bh[0], bh[2]);
            MMA4(d[j+1], ah, bh[1], bh[3]);
            MMA4(d[j],   ah, bl[0], bl[2]);
            MMA4(d[j+1], ah, bl[1], bl[3]);
            MMA4(d[j],   al, bh[0], bh[2]);
            MMA4(d[j+1], al, bh[1], bh[3]);
        }
    }
}

__global__ __launch_bounds__(128, 2)
void vitblock_mma(const float* __restrict__ x,
                  const float* __restrict__ qkv_b,
                  const float* __restrict__ conv_w,
                  const float* __restrict__ conv_b,
                  const float* __restrict__ out_b,
                  float* __restrict__ out)
{
    extern __shared__ char smem[];
    const uint32_t sb = smem_u32(smem);
    const int tid = threadIdx.x;
    const int w = tid >> 5, lane = tid & 31;
    const int lr = lane & 15, lc = lane >> 4;
    const int c2 = (lane & 3) * 2;
    const int r0 = 16 * w + (lane >> 2);

    const int wv0 = blockIdx.x & 31;
    const int wh  = (blockIdx.x >> 5) & 31;
    const int bI  = blockIdx.x >> 10;
    const float* xg = x + ((size_t)bI * 96) * 65536 + (size_t)(wh * 8) * 256 + wv0 * 8;

    // ---- P0: async Wk half0; stage consts + X ----
    stage_half(sb, 1, 0, tid);
    for (int i = tid; i < 288; i += 128) *(float*)(smem + O_QB + i * 4) = qkv_b[i];
    for (int i = tid; i < 864; i += 128) {
        int ch = i / 9, tap = i - ch * 9;
        *(float*)(smem + O_CW + (tap * 96 + ch) * 4) = conv_w[i];
    }
    if (tid < 96) {
        *(float*)(smem + O_CB + tid * 4) = conv_b[tid];
        *(float*)(smem + O_OB + tid * 4) = out_b[tid];
    }
    #pragma unroll
    for (int it = 0; it < 12; it++) {
        int e = it * 128 + tid;          // 1536 = 24 c4 x 64 tok
        int c4 = e >> 6, t = e & 63;
        const float* p = xg + (size_t)(c4 * 4) * 65536 + (t >> 3) * 256 + (t & 7);
        float v0 = p[0], v1 = p[65536], v2 = p[131072], v3 = p[196608];
        __nv_bfloat16 h0 = __float2bfloat16(v0), h1 = __float2bfloat16(v1);
        __nv_bfloat16 h2 = __float2bfloat16(v2), h3 = __float2bfloat16(v3);
        uint2 H = { bpack(h0, h1), bpack(h2, h3) };
        uint2 L = { bpack(__float2bfloat16(v0 - __bfloat162float(h0)),
                          __float2bfloat16(v1 - __bfloat162float(h1))),
                    bpack(__float2bfloat16(v2 - __bfloat162float(h2)),
                          __float2bfloat16(v3 - __bfloat162float(h3))) };
        uint32_t off = (uint32_t)(t * XS + c4 * 4) << 1;
        *(uint2*)(smem + O_X + off) = H;
        *(uint2*)(smem + O_X + XLO2 + off) = L;
    }

    // ---- GEMM K ----
    float dk[12][4];
    #pragma unroll
    for (int j = 0; j < 12; j++) { dk[j][0]=0.f; dk[j][1]=0.f; dk[j][2]=0.f; dk[j][3]=0.f; }
    CP_WAIT0(); __syncthreads();
    gemm_half(sb, 0, w, lane, dk);
    __syncthreads();
    stage_half(sb, 1, 1, tid);
    CP_WAIT0(); __syncthreads();
    gemm_half(sb, 1, w, lane, dk);
    __syncthreads();
    stage_half(sb, 0, 0, tid);          // Wq h0 (overlaps K stores)
    #pragma unroll
    for (int j = 0; j < 12; j++) {
        int col = 8 * j + c2;
        float2 bk = *(float2*)(smem + O_QB + (96 + col) * 4);
        #pragma unroll
        for (int h = 0; h < 2; h++) {
            int row = r0 + 8 * h;
            uint32_t hh, ll;
            split2(dk[j][2*h] + bk.x, dk[j][2*h+1] + bk.y, hh, ll);
            uint32_t o0 = (uint32_t)(row * XS + col) << 1;
            *(uint32_t*)(smem + O_K + o0) = hh;
            *(uint32_t*)(smem + O_K + KLO2 + o0) = ll;
        }
    }

    // ---- GEMM Q (fragments stay in registers) ----
    float dq[12][4];
    #pragma unroll
    for (int j = 0; j < 12; j++) { dq[j][0]=0.f; dq[j][1]=0.f; dq[j][2]=0.f; dq[j][3]=0.f; }
    CP_WAIT0(); __syncthreads();
    gemm_half(sb, 0, w, lane, dq);
    __syncthreads();
    stage_half(sb, 0, 1, tid);
    CP_WAIT0(); __syncthreads();
    gemm_half(sb, 1, w, lane, dq);
    __syncthreads();
    stage_half(sb, 2, 0, tid);          // Wv h0 (overlaps Q packing)
    uint32_t qh[6][4], ql[6][4];
    #pragma unroll
    for (int jj = 0; jj < 6; jj++) {
        int ta = 2 * jj, tb = 2 * jj + 1;
        float2 ba = *(float2*)(smem + O_QB + (8 * ta + c2) * 4);
        float2 bb = *(float2*)(smem + O_QB + (8 * tb + c2) * 4);
        split2((dq[ta][0] + ba.x) * SCALE_Q, (dq[ta][1] + ba.y) * SCALE_Q, qh[jj][0], ql[jj][0]);
        split2((dq[ta][2] + ba.x) * SCALE_Q, (dq[ta][3] + ba.y) * SCALE_Q, qh[jj][1], ql[jj][1]);
        split2((dq[tb][0] + bb.x) * SCALE_Q, (dq[tb][1] + bb.y) * SCALE_Q, qh[jj][2], ql[jj][2]);
        split2((dq[tb][2] + bb.x) * SCALE_Q, (dq[tb][3] + bb.y) * SCALE_Q, qh[jj][3], ql[jj][3]);
    }

    // ---- GEMM V ----
    float dv[12][4];
    #pragma unroll
    for (int j = 0; j < 12; j++) { dv[j][0]=0.f; dv[j][1]=0.f; dv[j][2]=0.f; dv[j][3]=0.f; }
    CP_WAIT0(); __syncthreads();
    gemm_half(sb, 0, w, lane, dv);
    __syncthreads();
    stage_half(sb, 2, 1, tid);
    CP_WAIT0(); __syncthreads();
    gemm_half(sb, 1, w, lane, dv);
    __syncthreads();                    // X dead from here
    stage_half(sb, 3, 0, tid);          // Wout h0 (hidden behind attention)
    #pragma unroll
    for (int j = 0; j < 12; j++) {
        int col = 8 * j + c2;
        float2 bv = *(float2*)(smem + O_QB + (192 + col) * 4);
        #pragma unroll
        for (int h = 0; h < 2; h++) {
            int row = r0 + 8 * h;
            float va = dv[j][2*h] + bv.x, vb = dv[j][2*h+1] + bv.y;
            float2 vf = { va, vb };
            *(float2*)(smem + O_X + ((row * FS + col) << 2)) = vf;   // v fp32 (LePE)
            uint32_t hh, ll;
            split2(va, vb, hh, ll);
            uint32_t o0 = (uint32_t)(row * XS + col) << 1;
            *(uint32_t*)(smem + O_V + o0) = hh;
            *(uint32_t*)(smem + O_V + VLO2 + o0) = ll;
        }
    }
    __syncthreads();                    // V + v visible to all warps

    // ---- scores S = Q'K^T (64x64) ----
    float s[8][4];
    #pragma unroll
    for (int j = 0; j < 8; j++) { s[j][0]=0.f; s[j][1]=0.f; s[j][2]=0.f; s[j][3]=0.f; }
    #pragma unroll
    for (int k = 0; k < 6; k++) {
        #pragma unroll
        for (int np = 0; np < 4; np++) {
            uint32_t bh[4], bl[4];
            uint32_t ba = sb + O_K + (((np * 16 + lr) * XS + k * 16 + lc * 8) << 1);
            ldm4(ba, bh);
            ldm4(ba + KLO2, bl);
            MMA4(s[2*np],   qh[k], bh[0], bh[2]);
            MMA4(s[2*np+1], qh[k], bh[1], bh[3]);
            MMA4(s[2*np],   qh[k], bl[0], bl[2]);
            MMA4(s[2*np+1], qh[k], bl[1], bl[3]);
            MMA4(s[2*np],   ql[k], bh[0], bh[2]);
            MMA4(s[2*np+1], ql[k], bh[1], bh[3]);
        }
    }

    // ---- softmax in registers ----
    {
        float mx0 = -1e30f, mx1 = -1e30f;
        #pragma unroll
        for (int j = 0; j < 8; j++) {
            mx0 = fmaxf(mx0, fmaxf(s[j][0], s[j][1]));
            mx1 = fmaxf(mx1, fmaxf(s[j][2], s[j][3]));
        }
        mx0 = fmaxf(mx0, __shfl_xor_sync(0xffffffffu, mx0, 1));
        mx0 = fmaxf(mx0, __shfl_xor_sync(0xffffffffu, mx0, 2));
        mx1 = fmaxf(mx1, __shfl_xor_sync(0xffffffffu, mx1, 1));
        mx1 = fmaxf(mx1, __shfl_xor_sync(0xffffffffu, mx1, 2));
        float s0 = 0.f, s1 = 0.f;
        #pragma unroll
        for (int j = 0; j < 8; j++) {
            s[j][0] = __expf(s[j][0] - mx0); s[j][1] = __expf(s[j][1] - mx0);
            s[j][2] = __expf(s[j][2] - mx1); s[j][3] = __expf(s[j][3] - mx1);
            s0 += s[j][0] + s[j][1];
            s1 += s[j][2] + s[j][3];
        }
        s0 += __shfl_xor_sync(0xffffffffu, s0, 1);
        s0 += __shfl_xor_sync(0xffffffffu, s0, 2);
        s1 += __shfl_xor_sync(0xffffffffu, s1, 1);
        s1 += __shfl_xor_sync(0xffffffffu, s1, 2);
        float i0 = 1.0f / s0, i1 = 1.0f / s1;
        #pragma unroll
        for (int j = 0; j < 8; j++) {
            s[j][0] *= i0; s[j][1] *= i0; s[j][2] *= i1; s[j][3] *= i1;
        }
    }
    uint32_t ph[4][4], pl[4][4];
    #pragma unroll
    for (int jj = 0; jj < 4; jj++) {
        split2(s[2*jj][0],   s[2*jj][1],   ph[jj][0], pl[jj][0]);
        split2(s[2*jj][2],   s[2*jj][3],   ph[jj][1], pl[jj][1]);
        split2(s[2*jj+1][0], s[2*jj+1][1], ph[jj][2], pl[jj][2]);
        split2(s[2*jj+1][2], s[2*jj+1][3], ph[jj][3], pl[jj][3]);
    }

    // ---- PV: O = P @ V  (V tok-major, ldmatrix.trans) ----
    // lane group g: tok = k*16 + (g>>1)*8 + (lane&7), ch = nb*16 + (g&1)*8
    float o[12][4];
    #pragma unroll
    for (int j = 0; j < 12; j++) { o[j][0]=0.f; o[j][1]=0.f; o[j][2]=0.f; o[j][3]=0.f; }
    {
        const int g = lane >> 3;
        const int tokoff = ((g >> 1) << 3) + (lane & 7);
        const int choff  = (g & 1) << 3;
        #pragma unroll
        for (int k = 0; k < 4; k++) {
            #pragma unroll
            for (int nb = 0; nb < 6; nb++) {
                uint32_t bh[4], bl[4];
                uint32_t ba = sb + O_V + (((k * 16 + tokoff) * XS + nb * 16 + choff) << 1);
                ldm4t(ba, bh);
                ldm4t(ba + VLO2, bl);
                MMA4(o[2*nb],   ph[k], bh[0], bh[2]);
                MMA4(o[2*nb+1], ph[k], bh[1], bh[3]);
                MMA4(o[2*nb],   ph[k], bl[0], bl[2]);
                MMA4(o[2*nb+1], ph[k], bl[1], bl[3]);
                MMA4(o[2*nb],   pl[k], bh[0], bh[2]);
                MMA4(o[2*nb+1], pl[k], bh[1], bh[3]);
            }
        }
    }

    // ---- O' = O + LePE + conv_b; repack to A-frags ----
    uint32_t oh[6][4], ol[6][4];
    {
        #pragma unroll
        for (int j = 0; j < 12; j++) {
            int c0 = 8 * j + c2;
            float2 cb2 = *(float2*)(smem + O_CB + c0 * 4);
            float2 cw2[9];
            #pragma unroll
            for (int tap = 0; tap < 9; tap++)
                cw2[tap] = *(float2*)(smem + O_CW + (tap * 96 + c0) * 4);
            #pragma unroll
            for (int h = 0; h < 2; h++) {
                int row = r0 + 8 * h;
                int y = row >> 3, xx = row & 7;
                float ax = o[j][2*h] + cb2.x, ay = o[j][2*h+1] + cb2.y;
                #pragma unroll
                for (int dy = -1; dy <= 1; dy++) {
                    int yy = y + dy;
                    if ((unsigned)yy > 7u) continue;
                    #pragma unroll
                    for (int dx = -1; dx <= 1; dx++) {
                        int xc = xx + dx;
                        if ((unsigned)xc > 7u) continue;
                        int nb = yy * 8 + xc;
                        float2 v2 = *(float2*)(smem + O_X + ((nb * FS + c0) << 2));
                        float2 cw = cw2[(dy + 1) * 3 + (dx + 1)];
                        ax += v2.x * cw.x;
                        ay += v2.y * cw.y;
                    }
                }
                o[j][2*h] = ax; o[j][2*h+1] = ay;
            }
        }
        #pragma unroll
        for (int jj = 0; jj < 6; jj++) {
            split2(o[2*jj][0],   o[2*jj][1],   oh[jj][0], ol[jj][0]);
            split2(o[2*jj][2],   o[2*jj][3],   oh[jj][1], ol[jj][1]);
            split2(o[2*jj+1][0], o[2*jj+1][1], oh[jj][2], ol[jj][2]);
            split2(o[2*jj+1][2], o[2*jj+1][3], oh[jj][3], ol[jj][3]);
        }
    }

    // ---- GEMM3: out = O' @ out_w^T + out_b ----
    float f[12][4];
    #pragma unroll
    for (int j = 0; j < 12; j++) { f[j][0]=0.f; f[j][1]=0.f; f[j][2]=0.f; f[j][3]=0.f; }
    CP_WAIT0(); __syncthreads();        // Wout h0 present; LePE reads done
    #pragma unroll
    for (int k = 0; k < 6; k++) {
        #pragma unroll
        for (int ni = 0; ni < 3; ni++) {
            uint32_t bh[4], bl[4];
            uint32_t ba = sb + O_W + (((ni * 16 + lr) * XS + k * 16 + lc * 8) << 1);
            ldm4(ba, bh);
            ldm4(ba + WLO2, bl);
            int j = 2 * ni;
            MMA4(f[j],   oh[k], bh[0], bh[2]);
            MMA4(f[j+1], oh[k], bh[1], bh[3]);
            MMA4(f[j],   oh[k], bl[0], bl[2]);
            MMA4(f[j+1], oh[k], bl[1], bl[3]);
            MMA4(f[j],   ol[k], bh[0], bh[2]);
            MMA4(f[j+1], ol[k], bh[1], bh[3]);
        }
    }
    __syncthreads();
    stage_half(sb, 3, 1, tid);
    CP_WAIT0(); __syncthreads();
    #pragma unroll
    for (int k = 0; k < 6; k++) {
        #pragma unroll
        for (int ni = 0; ni < 3; ni++) {
            uint32_t bh[4], bl[4];
            uint32_t ba = sb + O_W + (((ni * 16 + lr) * XS + k * 16 + lc * 8) << 1);
            ldm4(ba, bh);
            ldm4(ba + WLO2, bl);
            int j = 6 + 2 * ni;
            MMA4(f[j],   oh[k], bh[0], bh[2]);
            MMA4(f[j+1], oh[k], bh[1], bh[3]);
            MMA4(f[j],   oh[k], bl[0], bl[2]);
            MMA4(f[j+1], oh[k], bl[1], bl[3]);
            MMA4(f[j],   ol[k], bh[0], bh[2]);
            MMA4(f[j+1], ol[k], bh[1], bh[3]);
        }
    }
    __syncthreads();                    // v fp32 dead -> outstage
    #pragma unroll
    for (int j = 0; j < 12; j++) {
        float2 bo = *(float2*)(smem + O_OB + (8 * j + c2) * 4);
        float2 a = { f[j][0] + bo.x, f[j][1] + bo.y };
        float2 b = { f[j][2] + bo.x, f[j][3] + bo.y };
        *(float2*)(smem + O_X + ((r0 * FS + 8 * j + c2) << 2)) = a;
        *(float2*)(smem + O_X + (((r0 + 8) * FS + 8 * j + c2) << 2)) = b;
    }
    __syncthreads();

    // ---- coalesced writeout ----
    float* og = out + ((size_t)bI * 96) * 65536 + (size_t)(wh * 8) * 256 + wv0 * 8;
    #pragma unroll
    for (int it = 0; it < 12; it++) {
        int e = it * 128 + tid;
        int c4 = e >> 6, t = e & 63;
        const float* st = (const float*)(smem + O_X) + t * FS + c4 * 4;
        float2 u = *(const float2*)st;
        float2 v = *(const float2*)(st + 2);
        float* g = og + (size_t)(c4 * 4) * 65536 + (t >> 3) * 256 + (t & 7);
        g[0] = u.x; g[65536] = u.y; g[131072] = v.x; g[196608] = v.y;
    }
}

extern "C" void kernel_launch(void* const* d_in, const int* in_sizes, int n_in,
                              void* d_out, int out_size) {
    const float* x      = (const float*)d_in[0];
    const float* qkv_w  = (const float*)d_in[1];
    const float* qkv_b  = (const float*)d_in[2];
    const float* conv_w = (const float*)d_in[3];
    const float* conv_b = (const float*)d_in[4];
    const float* out_w  = (const float*)d_in[5];
    const float* out_b  = (const float*)d_in[6];
    float* out = (float*)d_out;

    prep_w<<<36, 256>>>(qkv_w, out_w);
    cudaFuncSetAttribute(vitblock_mma,
                         cudaFuncAttributeMaxDynamicSharedMemorySize, SMEM_BYTES);
    vitblock_mma<<<8192, 128, SMEM_BYTES>>>(x, qkv_b, conv_w, conv_b, out_b, out);
}

// round 6
// speedup vs baseline: 2.8178x; 1.0423x over previous
#include <cuda_runtime.h>
#include <cuda_bf16.h>
#include <cstdint>

#define SCALE_Q 0.10206207261596575f   // 1/sqrt(96)
#define XS 104   // bf16 row stride (96 cols + 8 pad)
#define FS 98    // fp32 outstage stride

// ---- smem byte offsets (total 71936 -> 3 CTAs/SM) ----
#define O_QB 0          // qkv_b 288 f
#define O_CW 1152       // cwT[9][96]
#define O_CB 4608
#define O_OB 4992
#define O_X  5376       // X hi/lo [64][104]x2 = 26624; then V hi/lo; then outstage fp32
#define XLO2 13312
#define O_W  32000      // W third hi/lo [32][104]x2 = 13312
#define WLO3 6656
#define O_K  45312      // K hi/lo [64][104]x2 = 26624
#define KLO2 13312
#define SMEM_BYTES 71936

#define WTHIRD_BYTES 13312
__device__ __align__(16) unsigned char g_wc[4][3][WTHIRD_BYTES];  // Q,K,V,OUT x 3 thirds

__device__ __forceinline__ uint32_t smem_u32(const void* p) {
    uint32_t a;
    asm("{ .reg .u64 t; cvta.to.shared.u64 t, %1; cvt.u32.u64 %0, t; }" : "=r"(a) : "l"(p));
    return a;
}
__device__ __forceinline__ void ldm4(uint32_t a, uint32_t* r) {
    asm volatile("ldmatrix.sync.aligned.m8n8.x4.shared.b16 {%0,%1,%2,%3}, [%4];"
                 : "=r"(r[0]), "=r"(r[1]), "=r"(r[2]), "=r"(r[3]) : "r"(a));
}
__device__ __forceinline__ void ldm4t(uint32_t a, uint32_t* r) {
    asm volatile("ldmatrix.sync.aligned.m8n8.x4.trans.shared.b16 {%0,%1,%2,%3}, [%4];"
                 : "=r"(r[0]), "=r"(r[1]), "=r"(r[2]), "=r"(r[3]) : "r"(a));
}
#define MMA4(D, A, B0, B1) \
    asm volatile("mma.sync.aligned.m16n8k16.row.col.f32.bf16.bf16.f32 " \
        "{%0,%1,%2,%3},{%4,%5,%6,%7},{%8,%9},{%0,%1,%2,%3};" \
        : "+f"((D)[0]), "+f"((D)[1]), "+f"((D)[2]), "+f"((D)[3]) \
        : "r"((A)[0]), "r"((A)[1]), "r"((A)[2]), "r"((A)[3]), "r"(B0), "r"(B1))

__device__ __forceinline__ void cp16(uint32_t s, const void* g) {
    asm volatile("{ .reg .u64 gg; cvta.to.global.u64 gg, %1;\n\t"
                 "cp.async.cg.shared.global [%0], [gg], 16; }"
                 :: "r"(s), "l"(g) : "memory");
}
#define CP_COMMIT() asm volatile("cp.async.commit_group;" ::: "memory")
#define CP_WAIT0()  asm volatile("cp.async.wait_group 0;" ::: "memory")

__device__ __forceinline__ uint32_t bpack(__nv_bfloat16 a, __nv_bfloat16 b) {
    __nv_bfloat162 t = __halves2bfloat162(a, b);
    return *reinterpret_cast<uint32_t*>(&t);
}
__device__ __forceinline__ void split2(float a, float b, uint32_t& h, uint32_t& l) {
    __nv_bfloat16 ha = __float2bfloat16(a), hb = __float2bfloat16(b);
    h = bpack(ha, hb);
    l = bpack(__float2bfloat16(a - __bfloat162float(ha)),
              __float2bfloat16(b - __bfloat162float(hb)));
}

// ---- prep: convert weights to hi/lo bf16 third images ----
__global__ void prep_w(const float* __restrict__ qkv_w, const float* __restrict__ out_w) {
    int e = blockIdx.x * 256 + threadIdx.x;
    if (e >= 4 * 2304) return;
    int chunk = e / 2304, r = e - chunk * 2304;
    int o = r / 24, q = r - o * 24;
    const float* src = (chunk < 3 ? qkv_w + chunk * 9216 : out_w) + o * 96 + q * 4;
    float4 v = *(const float4*)src;
    __nv_bfloat16 h0 = __float2bfloat16(v.x), h1 = __float2bfloat16(v.y);
    __nv_bfloat16 h2 = __float2bfloat16(v.z), h3 = __float2bfloat16(v.w);
    uint2 H = { bpack(h0, h1), bpack(h2, h3) };
    uint2 L = { bpack(__float2bfloat16(v.x - __bfloat162float(h0)),
                      __float2bfloat16(v.y - __bfloat162float(h1))),
                bpack(__float2bfloat16(v.z - __bfloat162float(h2)),
                      __float2bfloat16(v.w - __bfloat162float(h3))) };
    int th = o >> 5, lr = o & 31;
    uint32_t off = (uint32_t)(lr * XS + q * 4) << 1;
    *(uint2*)(g_wc[chunk][th] + off) = H;
    *(uint2*)(g_wc[chunk][th] + WLO3 + off) = L;
}

__device__ __forceinline__ void stage_third(uint32_t sb, int chunk, int th, int tid) {
    const unsigned char* g = g_wc[chunk][th];
    #pragma unroll
    for (int i = 0; i < 7; i++) {
        int e = i * 128 + tid;
        if (e < WTHIRD_BYTES / 16) cp16(sb + O_W + e * 16, g + e * 16);
    }
    CP_COMMIT();
}

// one 32-col third of a projection GEMM: warp w does rows [16w,16w+16)
__device__ __forceinline__ void gemm_third(uint32_t sb, int t, int w, int lane,
                                           float d[12][4]) {
    const int lr = lane & 15, lc = lane >> 4;
    #pragma unroll
    for (int k = 0; k < 6; k++) {
        uint32_t ah[4], al[4];
        uint32_t aa = sb + O_X + (((w * 16 + lr) * XS + k * 16 + lc * 8) << 1);
        ldm4(aa, ah);
        ldm4(aa + XLO2, al);
        #pragma unroll
        for (int ni = 0; ni < 2; ni++) {
            uint32_t bh[4], bl[4];
            uint32_t ba = sb + O_W + (((ni * 16 + lr) * XS + k * 16 + lc * 8) << 1);
            ldm4(ba, bh);
            ldm4(ba + WLO3, bl);
            int j = 4 * t + 2 * ni;
            MMA4(d[j],   ah, bh[0], bh[2]);
            MMA4(d[j+1], ah, bh[1], bh[3]);
            MMA4(d[j],   ah, bl[0], bl[2]);
            MMA4(d[j+1], ah, bl[1], bl[3]);
            MMA4(d[j],   al, bh[0], bh[2]);
            MMA4(d[j+1], al, bh[1], bh[3]);
        }
    }
}

__global__ __launch_bounds__(128, 3)
void vitblock_mma(const float* __restrict__ x,
                  const float* __restrict__ qkv_b,
                  const float* __restrict__ conv_w,
                  const float* __restrict__ conv_b,
                  const float* __restrict__ out_b,
                  float* __restrict__ out)
{
    extern __shared__ char smem[];
    const uint32_t sb = smem_u32(smem);
    const int tid = threadIdx.x;
    const int w = tid >> 5, lane = tid & 31;
    const int lr = lane & 15, lc = lane >> 4;
    const int c2 = (lane & 3) * 2;
    const int r0 = 16 * w + (lane >> 2);

    const int wv0 = blockIdx.x & 31;
    const int wh  = (blockIdx.x >> 5) & 31;
    const int bI  = blockIdx.x >> 10;
    const float* xg = x + ((size_t)bI * 96) * 65536 + (size_t)(wh * 8) * 256 + wv0 * 8;

    // ---- P0: async Wk third0; stage consts + X ----
    stage_third(sb, 1, 0, tid);
    for (int i = tid; i < 288; i += 128) *(float*)(smem + O_QB + i * 4) = qkv_b[i];
    for (int i = tid; i < 864; i += 128) {
        int ch = i / 9, tap = i - ch * 9;
        *(float*)(smem + O_CW + (tap * 96 + ch) * 4) = conv_w[i];
    }
    if (tid < 96) {
        *(float*)(smem + O_CB + tid * 4) = conv_b[tid];
        *(float*)(smem + O_OB + tid * 4) = out_b[tid];
    }
    #pragma unroll
    for (int it = 0; it < 12; it++) {
        int e = it * 128 + tid;          // 1536 = 24 c4 x 64 tok
        int c4 = e >> 6, t = e & 63;
        const float* p = xg + (size_t)(c4 * 4) * 65536 + (t >> 3) * 256 + (t & 7);
        float v0 = p[0], v1 = p[65536], v2 = p[131072], v3 = p[196608];
        __nv_bfloat16 h0 = __float2bfloat16(v0), h1 = __float2bfloat16(v1);
        __nv_bfloat16 h2 = __float2bfloat16(v2), h3 = __float2bfloat16(v3);
        uint2 H = { bpack(h0, h1), bpack(h2, h3) };
        uint2 L = { bpack(__float2bfloat16(v0 - __bfloat162float(h0)),
                          __float2bfloat16(v1 - __bfloat162float(h1))),
                    bpack(__float2bfloat16(v2 - __bfloat162float(h2)),
                          __float2bfloat16(v3 - __bfloat162float(h3))) };
        uint32_t off = (uint32_t)(t * XS + c4 * 4) << 1;
        *(uint2*)(smem + O_X + off) = H;
        *(uint2*)(smem + O_X + XLO2 + off) = L;
    }

    // ---- GEMM K (chunk 1) ----
    float dk[12][4];
    #pragma unroll
    for (int j = 0; j < 12; j++) { dk[j][0]=0.f; dk[j][1]=0.f; dk[j][2]=0.f; dk[j][3]=0.f; }
    #pragma unroll
    for (int t = 0; t < 3; t++) {
        CP_WAIT0(); __syncthreads();
        gemm_third(sb, t, w, lane, dk);
        __syncthreads();
        if (t < 2) stage_third(sb, 1, t + 1, tid);
        else       stage_third(sb, 0, 0, tid);     // Wq third0
    }
    // store K hi/lo (overlaps Wq cp.async)
    #pragma unroll
    for (int j = 0; j < 12; j++) {
        int col = 8 * j + c2;
        float2 bk = *(float2*)(smem + O_QB + (96 + col) * 4);
        #pragma unroll
        for (int h = 0; h < 2; h++) {
            int row = r0 + 8 * h;
            uint32_t hh, ll;
            split2(dk[j][2*h] + bk.x, dk[j][2*h+1] + bk.y, hh, ll);
            uint32_t o0 = (uint32_t)(row * XS + col) << 1;
            *(uint32_t*)(smem + O_K + o0) = hh;
            *(uint32_t*)(smem + O_K + KLO2 + o0) = ll;
        }
    }

    // ---- GEMM Q (chunk 0; fragments stay in registers) ----
    float dq[12][4];
    #pragma unroll
    for (int j = 0; j < 12; j++) { dq[j][0]=0.f; dq[j][1]=0.f; dq[j][2]=0.f; dq[j][3]=0.f; }
    #pragma unroll
    for (int t = 0; t < 3; t++) {
        CP_WAIT0(); __syncthreads();
        gemm_third(sb, t, w, lane, dq);
        __syncthreads();
        if (t < 2) stage_third(sb, 0, t + 1, tid);
        else       stage_third(sb, 2, 0, tid);     // Wv third0
    }
    uint32_t qh[6][4], ql[6][4];
    #pragma unroll
    for (int jj = 0; jj < 6; jj++) {
        int ta = 2 * jj, tb = 2 * jj + 1;
        float2 ba = *(float2*)(smem + O_QB + (8 * ta + c2) * 4);
        float2 bb = *(float2*)(smem + O_QB + (8 * tb + c2) * 4);
        split2((dq[ta][0] + ba.x) * SCALE_Q, (dq[ta][1] + ba.y) * SCALE_Q, qh[jj][0], ql[jj][0]);
        split2((dq[ta][2] + ba.x) * SCALE_Q, (dq[ta][3] + ba.y) * SCALE_Q, qh[jj][1], ql[jj][1]);
        split2((dq[tb][0] + bb.x) * SCALE_Q, (dq[tb][1] + bb.y) * SCALE_Q, qh[jj][2], ql[jj][2]);
        split2((dq[tb][2] + bb.x) * SCALE_Q, (dq[tb][3] + bb.y) * SCALE_Q, qh[jj][3], ql[jj][3]);
    }

    // ---- GEMM V (chunk 2) ----
    float dv[12][4];
    #pragma unroll
    for (int j = 0; j < 12; j++) { dv[j][0]=0.f; dv[j][1]=0.f; dv[j][2]=0.f; dv[j][3]=0.f; }
    #pragma unroll
    for (int t = 0; t < 3; t++) {
        CP_WAIT0(); __syncthreads();
        gemm_third(sb, t, w, lane, dv);
        __syncthreads();
        if (t < 2) stage_third(sb, 2, t + 1, tid);
        else       stage_third(sb, 3, 0, tid);     // Wout third0 (hidden behind attention)
    }
    // X dead -> write V hi/lo into X region (tok-major)
    #pragma unroll
    for (int j = 0; j < 12; j++) {
        int col = 8 * j + c2;
        float2 bv = *(float2*)(smem + O_QB + (192 + col) * 4);
        #pragma unroll
        for (int h = 0; h < 2; h++) {
            int row = r0 + 8 * h;
            uint32_t hh, ll;
            split2(dv[j][2*h] + bv.x, dv[j][2*h+1] + bv.y, hh, ll);
            uint32_t o0 = (uint32_t)(row * XS + col) << 1;
            *(uint32_t*)(smem + O_X + o0) = hh;
            *(uint32_t*)(smem + O_X + XLO2 + o0) = ll;
        }
    }
    __syncthreads();                    // V visible to all warps

    // ---- scores S = Q'K^T (64x64) ----
    float s[8][4];
    #pragma unroll
    for (int j = 0; j < 8; j++) { s[j][0]=0.f; s[j][1]=0.f; s[j][2]=0.f; s[j][3]=0.f; }
    #pragma unroll
    for (int k = 0; k < 6; k++) {
        #pragma unroll
        for (int np = 0; np < 4; np++) {
            uint32_t bh[4], bl[4];
            uint32_t ba = sb + O_K + (((np * 16 + lr) * XS + k * 16 + lc * 8) << 1);
            ldm4(ba, bh);
            ldm4(ba + KLO2, bl);
            MMA4(s[2*np],   qh[k], bh[0], bh[2]);
            MMA4(s[2*np+1], qh[k], bh[1], bh[3]);
            MMA4(s[2*np],   qh[k], bl[0], bl[2]);
            MMA4(s[2*np+1], qh[k], bl[1], bl[3]);
            MMA4(s[2*np],   ql[k], bh[0], bh[2]);
            MMA4(s[2*np+1], ql[k], bh[1], bh[3]);
        }
    }

    // ---- softmax in registers ----
    {
        float mx0 = -1e30f, mx1 = -1e30f;
        #pragma unroll
        for (int j = 0; j < 8; j++) {
            mx0 = fmaxf(mx0, fmaxf(s[j][0], s[j][1]));
            mx1 = fmaxf(mx1, fmaxf(s[j][2], s[j][3]));
        }
        mx0 = fmaxf(mx0, __shfl_xor_sync(0xffffffffu, mx0, 1));
        mx0 = fmaxf(mx0, __shfl_xor_sync(0xffffffffu, mx0, 2));
        mx1 = fmaxf(mx1, __shfl_xor_sync(0xffffffffu, mx1, 1));
        mx1 = fmaxf(mx1, __shfl_xor_sync(0xffffffffu, mx1, 2));
        float s0 = 0.f, s1 = 0.f;
        #pragma unroll
        for (int j = 0; j < 8; j++) {
            s[j][0] = __expf(s[j][0] - mx0); s[j][1] = __expf(s[j][1] - mx0);
            s[j][2] = __expf(s[j][2] - mx1); s[j][3] = __expf(s[j][3] - mx1);
            s0 += s[j][0] + s[j][1];
            s1 += s[j][2] + s[j][3];
        }
        s0 += __shfl_xor_sync(0xffffffffu, s0, 1);
        s0 += __shfl_xor_sync(0xffffffffu, s0, 2);
        s1 += __shfl_xor_sync(0xffffffffu, s1, 1);
        s1 += __shfl_xor_sync(0xffffffffu, s1, 2);
        float i0 = 1.0f / s0, i1 = 1.0f / s1;
        #pragma unroll
        for (int j = 0; j < 8; j++) {
            s[j][0] *= i0; s[j][1] *= i0; s[j][2] *= i1; s[j][3] *= i1;
        }
    }
    uint32_t ph[4][4], pl[4][4];
    #pragma unroll
    for (int jj = 0; jj < 4; jj++) {
        split2(s[2*jj][0],   s[2*jj][1],   ph[jj][0], pl[jj][0]);
        split2(s[2*jj][2],   s[2*jj][3],   ph[jj][1], pl[jj][1]);
        split2(s[2*jj+1][0], s[2*jj+1][1], ph[jj][2], pl[jj][2]);
        split2(s[2*jj+1][2], s[2*jj+1][3], ph[jj][3], pl[jj][3]);
    }

    // ---- PV: O = P @ V  (V tok-major in X region, ldmatrix.trans) ----
    float o[12][4];
    #pragma unroll
    for (int j = 0; j < 12; j++) { o[j][0]=0.f; o[j][1]=0.f; o[j][2]=0.f; o[j][3]=0.f; }
    {
        const int g = lane >> 3;
        const int tokoff = ((g >> 1) << 3) + (lane & 7);
        const int choff  = (g & 1) << 3;
        #pragma unroll
        for (int k = 0; k < 4; k++) {
            #pragma unroll
            for (int nb = 0; nb < 6; nb++) {
                uint32_t bh[4], bl[4];
                uint32_t ba = sb + O_X + (((k * 16 + tokoff) * XS + nb * 16 + choff) << 1);
                ldm4t(ba, bh);
                ldm4t(ba + XLO2, bl);
                MMA4(o[2*nb],   ph[k], bh[0], bh[2]);
                MMA4(o[2*nb+1], ph[k], bh[1], bh[3]);
                MMA4(o[2*nb],   ph[k], bl[0], bl[2]);
                MMA4(o[2*nb+1], ph[k], bl[1], bl[3]);
                MMA4(o[2*nb],   pl[k], bh[0], bh[2]);
                MMA4(o[2*nb+1], pl[k], bh[1], bh[3]);
            }
        }
    }

    // ---- O' = O + LePE + conv_b (v reconstructed from V hi+lo); repack to A-frags ----
    uint32_t oh[6][4], ol[6][4];
    {
        #pragma unroll
        for (int j = 0; j < 12; j++) {
            int c0 = 8 * j + c2;
            float2 cb2 = *(float2*)(smem + O_CB + c0 * 4);
            float2 cw2[9];
            #pragma unroll
            for (int tap = 0; tap < 9; tap++)
                cw2[tap] = *(float2*)(smem + O_CW + (tap * 96 + c0) * 4);
            #pragma unroll
            for (int h = 0; h < 2; h++) {
                int row = r0 + 8 * h;
                int y = row >> 3, xx = row & 7;
                float ax = o[j][2*h] + cb2.x, ay = o[j][2*h+1] + cb2.y;
                #pragma unroll
                for (int dy = -1; dy <= 1; dy++) {
                    int yy = y + dy;
                    if ((unsigned)yy > 7u) continue;
                    #pragma unroll
                    for (int dx = -1; dx <= 1; dx++) {
                        int xc = xx + dx;
                        if ((unsigned)xc > 7u) continue;
                        int nb = yy * 8 + xc;
                        uint32_t off = (uint32_t)(nb * XS + c0) << 1;
                        __nv_bfloat162 hv = *(__nv_bfloat162*)(smem + O_X + off);
                        __nv_bfloat162 lv = *(__nv_bfloat162*)(smem + O_X + XLO2 + off);
                        float2 cw = cw2[(dy + 1) * 3 + (dx + 1)];
                        ax += (__bfloat162float(hv.x) + __bfloat162float(lv.x)) * cw.x;
                        ay += (__bfloat162float(hv.y) + __bfloat162float(lv.y)) * cw.y;
                    }
                }
                o[j][2*h] = ax; o[j][2*h+1] = ay;
            }
        }
        #pragma unroll
        for (int jj = 0; jj < 6; jj++) {
            split2(o[2*jj][0],   o[2*jj][1],   oh[jj][0], ol[jj][0]);
            split2(o[2*jj][2],   o[2*jj][3],   oh[jj][1], ol[jj][1]);
            split2(o[2*jj+1][0], o[2*jj+1][1], oh[jj][2], ol[jj][2]);
            split2(o[2*jj+1][2], o[2*jj+1][3], oh[jj][3], ol[jj][3]);
        }
    }

    // ---- GEMM3: out = O' @ out_w^T + out_b (chunk 3, A in regs) ----
    float f[12][4];
    #pragma unroll
    for (int j = 0; j < 12; j++) { f[j][0]=0.f; f[j][1]=0.f; f[j][2]=0.f; f[j][3]=0.f; }
    #pragma unroll
    for (int t = 0; t < 3; t++) {
        CP_WAIT0(); __syncthreads();
        #pragma unroll
        for (int k = 0; k < 6; k++) {
            #pragma unroll
            for (int ni = 0; ni < 2; ni++) {
                uint32_t bh[4], bl[4];
                uint32_t ba = sb + O_W + (((ni * 16 + lr) * XS + k * 16 + lc * 8) << 1);
                ldm4(ba, bh);
                ldm4(ba + WLO3, bl);
                int j = 4 * t + 2 * ni;
                MMA4(f[j],   oh[k], bh[0], bh[2]);
                MMA4(f[j+1], oh[k], bh[1], bh[3]);
                MMA4(f[j],   oh[k], bl[0], bl[2]);
                MMA4(f[j+1], oh[k], bl[1], bl[3]);
                MMA4(f[j],   ol[k], bh[0], bh[2]);
                MMA4(f[j+1], ol[k], bh[1], bh[3]);
            }
        }
        __syncthreads();
        if (t < 2) stage_third(sb, 3, t + 1, tid);
    }
    // V dead -> outstage fp32 into X region
    #pragma unroll
    for (int j = 0; j < 12; j++) {
        float2 bo = *(float2*)(smem + O_OB + (8 * j + c2) * 4);
        float2 a = { f[j][0] + bo.x, f[j][1] + bo.y };
        float2 b = { f[j][2] + bo.x, f[j][3] + bo.y };
        *(float2*)(smem + O_X + ((r0 * FS + 8 * j + c2) << 2)) = a;
        *(float2*)(smem + O_X + (((r0 + 8) * FS + 8 * j + c2) << 2)) = b;
    }
    __syncthreads();

    // ---- coalesced writeout ----
    float* og = out + ((size_t)bI * 96) * 65536 + (size_t)(wh * 8) * 256 + wv0 * 8;
    #pragma unroll
    for (int it = 0; it < 12; it++) {
        int e = it * 128 + tid;
        int c4 = e >> 6, t = e & 63;
        const float* st = (const float*)(smem + O_X) + t * FS + c4 * 4;
        float2 u = *(const float2*)st;
        float2 v = *(const float2*)(st + 2);
        float* g = og + (size_t)(c4 * 4) * 65536 + (t >> 3) * 256 + (t & 7);
        g[0] = u.x; g[65536] = u.y; g[131072] = v.x; g[196608] = v.y;
    }
}

extern "C" void kernel_launch(void* const* d_in, const int* in_sizes, int n_in,
                              void* d_out, int out_size) {
    const float* x      = (const float*)d_in[0];
    const float* qkv_w  = (const float*)d_in[1];
    const float* qkv_b  = (const float*)d_in[2];
    const float* conv_w = (const float*)d_in[3];
    const float* conv_b = (const float*)d_in[4];
    const float* out_w  = (const float*)d_in[5];
    const float* out_b  = (const float*)d_in[6];
    float* out = (float*)d_out;

    prep_w<<<36, 256>>>(qkv_w, out_w);
    cudaFuncSetAttribute(vitblock_mma,
                         cudaFuncAttributeMaxDynamicSharedMemorySize, SMEM_BYTES);
    vitblock_mma<<<8192, 128, SMEM_BYTES>>>(x, qkv_b, conv_w, conv_b, out_b, out);
}

// round 7
// speedup vs baseline: 2.9582x; 1.0498x over previous
#include <cuda_runtime.h>
#include <cuda_bf16.h>
#include <cstdint>

#define SCALE_Q 0.10206207261596575f   // 1/sqrt(96)
#define XS 104   // bf16 row stride (96 cols + 8 pad)
#define FS 98    // fp32 outstage stride

// ---- smem byte offsets (total 53248 -> 4 CTAs/SM) ----
#define O_X  0          // X hi/lo [64][104]x2 = 26624; then V hi/lo; then outstage fp32
#define XLO2 13312
#define O_K  26624      // K hi/lo [64][104]x2 = 26624
#define KLO2 13312
#define SMEM_BYTES 53248

// W as pre-built MMA B-fragments: [chunk][k][ni][hi/lo][lane] (16B per lane)
__device__ __align__(16) uint4 g_wf[4][6][6][2][32];
__device__ __align__(8)  float g_cw[9][96];   // conv_w transposed [tap][ch]

__device__ __forceinline__ uint32_t smem_u32(const void* p) {
    uint32_t a;
    asm("{ .reg .u64 t; cvta.to.shared.u64 t, %1; cvt.u32.u64 %0, t; }" : "=r"(a) : "l"(p));
    return a;
}
__device__ __forceinline__ void ldm4(uint32_t a, uint32_t* r) {
    asm volatile("ldmatrix.sync.aligned.m8n8.x4.shared.b16 {%0,%1,%2,%3}, [%4];"
                 : "=r"(r[0]), "=r"(r[1]), "=r"(r[2]), "=r"(r[3]) : "r"(a));
}
__device__ __forceinline__ void ldm4t(uint32_t a, uint32_t* r) {
    asm volatile("ldmatrix.sync.aligned.m8n8.x4.trans.shared.b16 {%0,%1,%2,%3}, [%4];"
                 : "=r"(r[0]), "=r"(r[1]), "=r"(r[2]), "=r"(r[3]) : "r"(a));
}
#define MMA4(D, A, B0, B1) \
    asm volatile("mma.sync.aligned.m16n8k16.row.col.f32.bf16.bf16.f32 " \
        "{%0,%1,%2,%3},{%4,%5,%6,%7},{%8,%9},{%0,%1,%2,%3};" \
        : "+f"((D)[0]), "+f"((D)[1]), "+f"((D)[2]), "+f"((D)[3]) \
        : "r"((A)[0]), "r"((A)[1]), "r"((A)[2]), "r"((A)[3]), "r"(B0), "r"(B1))

__device__ __forceinline__ uint32_t bpack(__nv_bfloat16 a, __nv_bfloat16 b) {
    __nv_bfloat162 t = __halves2bfloat162(a, b);
    return *reinterpret_cast<uint32_t*>(&t);
}
__device__ __forceinline__ void split2(float a, float b, uint32_t& h, uint32_t& l) {
    __nv_bfloat16 ha = __float2bfloat16(a), hb = __float2bfloat16(b);
    h = bpack(ha, hb);
    l = bpack(__float2bfloat16(a - __bfloat162float(ha)),
              __float2bfloat16(b - __bfloat162float(hb)));
}

// ---- prep: build B-fragments (hi/lo) + transposed conv weights ----
__global__ void prep_w(const float* __restrict__ qkv_w, const float* __restrict__ out_w,
                       const float* __restrict__ conv_w) {
    int e = blockIdx.x * 256 + threadIdx.x;
    if (e < 4608) {                       // 4 chunks x 6 k x 6 ni x 32 lanes
        int lane = e & 31; int t = e >> 5;
        int ni = t % 6; t /= 6; int k = t % 6; int c = t / 6;
        const float* W = (c < 3 ? qkv_w + c * 9216 : out_w);
        int n0 = ni * 16 + (lane >> 2), n1 = n0 + 8;
        int kk = k * 16 + (lane & 3) * 2;
        uint32_t h0,l0,h1,l1,h2,l2,h3,l3;
        split2(W[n0*96+kk],   W[n0*96+kk+1], h0, l0);
        split2(W[n1*96+kk],   W[n1*96+kk+1], h1, l1);
        split2(W[n0*96+kk+8], W[n0*96+kk+9], h2, l2);
        split2(W[n1*96+kk+8], W[n1*96+kk+9], h3, l3);
        g_wf[c][k][ni][0][lane] = make_uint4(h0, h1, h2, h3);
        g_wf[c][k][ni][1][lane] = make_uint4(l0, l1, l2, l3);
    } else if (e < 4608 + 864) {
        int i = e - 4608;                 // conv_w [ch][tap] -> g_cw [tap][ch]
        int ch = i / 9, tap = i - ch * 9;
        g_cw[tap][ch] = conv_w[i];
    }
}

// projection GEMM: D[12][4] += (Xhi+Xlo) @ (Whi+Wlo)^T, B from global fragments
__device__ __forceinline__ void gemm_proj(uint32_t sb, int chunk, int w, int lane,
                                          float d[12][4]) {
    const int lr = lane & 15, lc = lane >> 4;
    #pragma unroll
    for (int k = 0; k < 6; k++) {
        uint32_t ah[4], al[4];
        uint32_t aa = sb + O_X + (((w * 16 + lr) * XS + k * 16 + lc * 8) << 1);
        ldm4(aa, ah);
        ldm4(aa + XLO2, al);
        #pragma unroll
        for (int ni = 0; ni < 6; ni++) {
            uint4 BH = __ldg(&g_wf[chunk][k][ni][0][lane]);
            uint4 BL = __ldg(&g_wf[chunk][k][ni][1][lane]);
            MMA4(d[2*ni],   ah, BH.x, BH.z);
            MMA4(d[2*ni+1], ah, BH.y, BH.w);
            MMA4(d[2*ni],   ah, BL.x, BL.z);
            MMA4(d[2*ni+1], ah, BL.y, BL.w);
            MMA4(d[2*ni],   al, BH.x, BH.z);
            MMA4(d[2*ni+1], al, BH.y, BH.w);
        }
    }
}

__global__ __launch_bounds__(128, 4)
void vitblock_mma(const float* __restrict__ x,
                  const float* __restrict__ qkv_b,
                  const float* __restrict__ conv_b,
                  const float* __restrict__ out_b,
                  float* __restrict__ out)
{
    extern __shared__ char smem[];
    const uint32_t sb = smem_u32(smem);
    const int tid = threadIdx.x;
    const int w = tid >> 5, lane = tid & 31;
    const int lr = lane & 15, lc = lane >> 4;
    const int c2 = (lane & 3) * 2;
    const int r0 = 16 * w + (lane >> 2);

    const int wv0 = blockIdx.x & 31;
    const int wh  = (blockIdx.x >> 5) & 31;
    const int bI  = blockIdx.x >> 10;
    const float* xg = x + ((size_t)bI * 96) * 65536 + (size_t)(wh * 8) * 256 + wv0 * 8;

    // ---- stage X hi/lo ----
    #pragma unroll
    for (int it = 0; it < 12; it++) {
        int e = it * 128 + tid;          // 1536 = 24 c4 x 64 tok
        int c4 = e >> 6, t = e & 63;
        const float* p = xg + (size_t)(c4 * 4) * 65536 + (t >> 3) * 256 + (t & 7);
        float v0 = p[0], v1 = p[65536], v2 = p[131072], v3 = p[196608];
        __nv_bfloat16 h0 = __float2bfloat16(v0), h1 = __float2bfloat16(v1);
        __nv_bfloat16 h2 = __float2bfloat16(v2), h3 = __float2bfloat16(v3);
        uint2 H = { bpack(h0, h1), bpack(h2, h3) };
        uint2 L = { bpack(__float2bfloat16(v0 - __bfloat162float(h0)),
                          __float2bfloat16(v1 - __bfloat162float(h1))),
                    bpack(__float2bfloat16(v2 - __bfloat162float(h2)),
                          __float2bfloat16(v3 - __bfloat162float(h3))) };
        uint32_t off = (uint32_t)(t * XS + c4 * 4) << 1;
        *(uint2*)(smem + O_X + off) = H;
        *(uint2*)(smem + O_X + XLO2 + off) = L;
    }
    __syncthreads();

    // ---- GEMM K -> K smem ----
    {
        float dk[12][4];
        #pragma unroll
        for (int j = 0; j < 12; j++) { dk[j][0]=0.f; dk[j][1]=0.f; dk[j][2]=0.f; dk[j][3]=0.f; }
        gemm_proj(sb, 1, w, lane, dk);
        #pragma unroll
        for (int j = 0; j < 12; j++) {
            int col = 8 * j + c2;
            float2 bk = __ldg((const float2*)(qkv_b + 96 + col));
            #pragma unroll
            for (int h = 0; h < 2; h++) {
                int row = r0 + 8 * h;
                uint32_t hh, ll;
                split2(dk[j][2*h] + bk.x, dk[j][2*h+1] + bk.y, hh, ll);
                uint32_t o0 = (uint32_t)(row * XS + col) << 1;
                *(uint32_t*)(smem + O_K + o0) = hh;
                *(uint32_t*)(smem + O_K + KLO2 + o0) = ll;
            }
        }
    }

    // ---- GEMM Q (fragments stay in registers) ----
    uint32_t qh[6][4], ql[6][4];
    {
        float dq[12][4];
        #pragma unroll
        for (int j = 0; j < 12; j++) { dq[j][0]=0.f; dq[j][1]=0.f; dq[j][2]=0.f; dq[j][3]=0.f; }
        gemm_proj(sb, 0, w, lane, dq);
        #pragma unroll
        for (int jj = 0; jj < 6; jj++) {
            int ta = 2 * jj, tb = 2 * jj + 1;
            float2 ba = __ldg((const float2*)(qkv_b + 8 * ta + c2));
            float2 bb = __ldg((const float2*)(qkv_b + 8 * tb + c2));
            split2((dq[ta][0] + ba.x) * SCALE_Q, (dq[ta][1] + ba.y) * SCALE_Q, qh[jj][0], ql[jj][0]);
            split2((dq[ta][2] + ba.x) * SCALE_Q, (dq[ta][3] + ba.y) * SCALE_Q, qh[jj][1], ql[jj][1]);
            split2((dq[tb][0] + bb.x) * SCALE_Q, (dq[tb][1] + bb.y) * SCALE_Q, qh[jj][2], ql[jj][2]);
            split2((dq[tb][2] + bb.x) * SCALE_Q, (dq[tb][3] + bb.y) * SCALE_Q, qh[jj][3], ql[jj][3]);
        }
    }

    // ---- GEMM V ----
    float dv[12][4];
    #pragma unroll
    for (int j = 0; j < 12; j++) { dv[j][0]=0.f; dv[j][1]=0.f; dv[j][2]=0.f; dv[j][3]=0.f; }
    gemm_proj(sb, 2, w, lane, dv);
    __syncthreads();                    // all warps done reading X
    // write V hi/lo into X region (tok-major)
    #pragma unroll
    for (int j = 0; j < 12; j++) {
        int col = 8 * j + c2;
        float2 bv = __ldg((const float2*)(qkv_b + 192 + col));
        #pragma unroll
        for (int h = 0; h < 2; h++) {
            int row = r0 + 8 * h;
            uint32_t hh, ll;
            split2(dv[j][2*h] + bv.x, dv[j][2*h+1] + bv.y, hh, ll);
            uint32_t o0 = (uint32_t)(row * XS + col) << 1;
            *(uint32_t*)(smem + O_X + o0) = hh;
            *(uint32_t*)(smem + O_X + XLO2 + o0) = ll;
        }
    }
    __syncthreads();                    // V + K visible to all warps

    // ---- scores S = Q'K^T (64x64) ----
    float s[8][4];
    #pragma unroll
    for (int j = 0; j < 8; j++) { s[j][0]=0.f; s[j][1]=0.f; s[j][2]=0.f; s[j][3]=0.f; }
    #pragma unroll
    for (int k = 0; k < 6; k++) {
        #pragma unroll
        for (int np = 0; np < 4; np++) {
            uint32_t bh[4], bl[4];
            uint32_t ba = sb + O_K + (((np * 16 + lr) * XS + k * 16 + lc * 8) << 1);
            ldm4(ba, bh);
            ldm4(ba + KLO2, bl);
            MMA4(s[2*np],   qh[k], bh[0], bh[2]);
            MMA4(s[2*np+1], qh[k], bh[1], bh[3]);
            MMA4(s[2*np],   qh[k], bl[0], bl[2]);
            MMA4(s[2*np+1], qh[k], bl[1], bl[3]);
            MMA4(s[2*np],   ql[k], bh[0], bh[2]);
            MMA4(s[2*np+1], ql[k], bh[1], bh[3]);
        }
    }

    // ---- softmax in registers ----
    {
        float mx0 = -1e30f, mx1 = -1e30f;
        #pragma unroll
        for (int j = 0; j < 8; j++) {
            mx0 = fmaxf(mx0, fmaxf(s[j][0], s[j][1]));
            mx1 = fmaxf(mx1, fmaxf(s[j][2], s[j][3]));
        }
        mx0 = fmaxf(mx0, __shfl_xor_sync(0xffffffffu, mx0, 1));
        mx0 = fmaxf(mx0, __shfl_xor_sync(0xffffffffu, mx0, 2));
        mx1 = fmaxf(mx1, __shfl_xor_sync(0xffffffffu, mx1, 1));
        mx1 = fmaxf(mx1, __shfl_xor_sync(0xffffffffu, mx1, 2));
        float s0 = 0.f, s1 = 0.f;
        #pragma unroll
        for (int j = 0; j < 8; j++) {
            s[j][0] = __expf(s[j][0] - mx0); s[j][1] = __expf(s[j][1] - mx0);
            s[j][2] = __expf(s[j][2] - mx1); s[j][3] = __expf(s[j][3] - mx1);
            s0 += s[j][0] + s[j][1];
            s1 += s[j][2] + s[j][3];
        }
        s0 += __shfl_xor_sync(0xffffffffu, s0, 1);
        s0 += __shfl_xor_sync(0xffffffffu, s0, 2);
        s1 += __shfl_xor_sync(0xffffffffu, s1, 1);
        s1 += __shfl_xor_sync(0xffffffffu, s1, 2);
        float i0 = 1.0f / s0, i1 = 1.0f / s1;
        #pragma unroll
        for (int j = 0; j < 8; j++) {
            s[j][0] *= i0; s[j][1] *= i0; s[j][2] *= i1; s[j][3] *= i1;
        }
    }
    uint32_t ph[4][4], pl[4][4];
    #pragma unroll
    for (int jj = 0; jj < 4; jj++) {
        split2(s[2*jj][0],   s[2*jj][1],   ph[jj][0], pl[jj][0]);
        split2(s[2*jj][2],   s[2*jj][3],   ph[jj][1], pl[jj][1]);
        split2(s[2*jj+1][0], s[2*jj+1][1], ph[jj][2], pl[jj][2]);
        split2(s[2*jj+1][2], s[2*jj+1][3], ph[jj][3], pl[jj][3]);
    }

    // ---- PV: O = P @ V  (V tok-major in X region, ldmatrix.trans) ----
    float o[12][4];
    #pragma unroll
    for (int j = 0; j < 12; j++) { o[j][0]=0.f; o[j][1]=0.f; o[j][2]=0.f; o[j][3]=0.f; }
    {
        const int g = lane >> 3;
        const int tokoff = ((g >> 1) << 3) + (lane & 7);
        const int choff  = (g & 1) << 3;
        #pragma unroll
        for (int k = 0; k < 4; k++) {
            #pragma unroll
            for (int nb = 0; nb < 6; nb++) {
                uint32_t bh[4], bl[4];
                uint32_t ba = sb + O_X + (((k * 16 + tokoff) * XS + nb * 16 + choff) << 1);
                ldm4t(ba, bh);
                ldm4t(ba + XLO2, bl);
                MMA4(o[2*nb],   ph[k], bh[0], bh[2]);
                MMA4(o[2*nb+1], ph[k], bh[1], bh[3]);
                MMA4(o[2*nb],   ph[k], bl[0], bl[2]);
                MMA4(o[2*nb+1], ph[k], bl[1], bl[3]);
                MMA4(o[2*nb],   pl[k], bh[0], bh[2]);
                MMA4(o[2*nb+1], pl[k], bh[1], bh[3]);
            }
        }
    }

    // ---- O' = O + LePE + conv_b (v from V hi+lo); repack to A-frags ----
    uint32_t oh[6][4], ol[6][4];
    {
        #pragma unroll
        for (int j = 0; j < 12; j++) {
            int c0 = 8 * j + c2;
            float2 cb2 = __ldg((const float2*)(conv_b + c0));
            #pragma unroll
            for (int h = 0; h < 2; h++) {
                int row = r0 + 8 * h;
                int y = row >> 3, xx = row & 7;
                float ax = o[j][2*h] + cb2.x, ay = o[j][2*h+1] + cb2.y;
                #pragma unroll
                for (int dy = -1; dy <= 1; dy++) {
                    int yy = y + dy;
                    if ((unsigned)yy > 7u) continue;
                    #pragma unroll
                    for (int dx = -1; dx <= 1; dx++) {
                        int xc = xx + dx;
                        if ((unsigned)xc > 7u) continue;
                        int nb = yy * 8 + xc;
                        uint32_t off = (uint32_t)(nb * XS + c0) << 1;
                        __nv_bfloat162 hv = *(__nv_bfloat162*)(smem + O_X + off);
                        __nv_bfloat162 lv = *(__nv_bfloat162*)(smem + O_X + XLO2 + off);
                        float2 cw = __ldg((const float2*)&g_cw[(dy + 1) * 3 + (dx + 1)][c0]);
                        ax += (__bfloat162float(hv.x) + __bfloat162float(lv.x)) * cw.x;
                        ay += (__bfloat162float(hv.y) + __bfloat162float(lv.y)) * cw.y;
                    }
                }
                o[j][2*h] = ax; o[j][2*h+1] = ay;
            }
        }
        #pragma unroll
        for (int jj = 0; jj < 6; jj++) {
            split2(o[2*jj][0],   o[2*jj][1],   oh[jj][0], ol[jj][0]);
            split2(o[2*jj][2],   o[2*jj][3],   oh[jj][1], ol[jj][1]);
            split2(o[2*jj+1][0], o[2*jj+1][1], oh[jj][2], ol[jj][2]);
            split2(o[2*jj+1][2], o[2*jj+1][3], oh[jj][3], ol[jj][3]);
        }
    }

    // ---- GEMM3: out = O' @ out_w^T + out_b (chunk 3, A in regs) ----
    float f[12][4];
    #pragma unroll
    for (int j = 0; j < 12; j++) { f[j][0]=0.f; f[j][1]=0.f; f[j][2]=0.f; f[j][3]=0.f; }
    #pragma unroll
    for (int k = 0; k < 6; k++) {
        #pragma unroll
        for (int ni = 0; ni < 6; ni++) {
            uint4 BH = __ldg(&g_wf[3][k][ni][0][lane]);
            uint4 BL = __ldg(&g_wf[3][k][ni][1][lane]);
            MMA4(f[2*ni],   oh[k], BH.x, BH.z);
            MMA4(f[2*ni+1], oh[k], BH.y, BH.w);
            MMA4(f[2*ni],   oh[k], BL.x, BL.z);
            MMA4(f[2*ni+1], oh[k], BL.y, BL.w);
            MMA4(f[2*ni],   ol[k], BH.x, BH.z);
            MMA4(f[2*ni+1], ol[k], BH.y, BH.w);
        }
    }
    __syncthreads();                    // V region dead -> outstage
    #pragma unroll
    for (int j = 0; j < 12; j++) {
        float2 bo = __ldg((const float2*)(out_b + 8 * j + c2));
        float2 a = { f[j][0] + bo.x, f[j][1] + bo.y };
        float2 b = { f[j][2] + bo.x, f[j][3] + bo.y };
        *(float2*)(smem + O_X + ((r0 * FS + 8 * j + c2) << 2)) = a;
        *(float2*)(smem + O_X + (((r0 + 8) * FS + 8 * j + c2) << 2)) = b;
    }
    __syncthreads();

    // ---- coalesced writeout ----
    float* og = out + ((size_t)bI * 96) * 65536 + (size_t)(wh * 8) * 256 + wv0 * 8;
    #pragma unroll
    for (int it = 0; it < 12; it++) {
        int e = it * 128 + tid;
        int c4 = e >> 6, t = e & 63;
        const float* st = (const float*)(smem + O_X) + t * FS + c4 * 4;
        float2 u = *(const float2*)st;
        float2 v = *(const float2*)(st + 2);
        float* g = og + (size_t)(c4 * 4) * 65536 + (t >> 3) * 256 + (t & 7);
        g[0] = u.x; g[65536] = u.y; g[131072] = v.x; g[196608] = v.y;
    }
}

extern "C" void kernel_launch(void* const* d_in, const int* in_sizes, int n_in,
                              void* d_out, int out_size) {
    const float* x      = (const float*)d_in[0];
    const float* qkv_w  = (const float*)d_in[1];
    const float* qkv_b  = (const float*)d_in[2];
    const float* conv_w = (const float*)d_in[3];
    const float* conv_b = (const float*)d_in[4];
    const float* out_w  = (const float*)d_in[5];
    const float* out_b  = (const float*)d_in[6];
    float* out = (float*)d_out;

    prep_w<<<22, 256>>>(qkv_w, out_w, conv_w);
    cudaFuncSetAttribute(vitblock_mma,
                         cudaFuncAttributeMaxDynamicSharedMemorySize, SMEM_BYTES);
    vitblock_mma<<<8192, 128, SMEM_BYTES>>>(x, qkv_b, conv_b, out_b, out);
}

// round 8
// speedup vs baseline: 4.4778x; 1.5137x over previous
#include <cuda_runtime.h>
#include <cuda_bf16.h>
#include <cstdint>

#define SCALE_Q 0.10206207261596575f   // 1/sqrt(96)
#define XS 104   // bf16 row stride (96 cols + 8 pad)
#define FS 98    // fp32 outstage stride

// ---- smem: X hi/lo [64][104]x2 = 26624 (later V hi/lo, later outstage fp32)
//            K hi    [64][104]   = 13312
#define O_X  0
#define XLO2 13312
#define O_K  26624
#define SMEM_BYTES 39936

// W as pre-built MMA B-fragments: [chunk][k][ni][hi/lo][lane] (16B per lane)
__device__ __align__(16) uint4 g_wf[4][6][6][2][32];
__device__ __align__(8)  float g_cw[9][96];   // conv_w transposed [tap][ch]

__device__ __forceinline__ uint32_t smem_u32(const void* p) {
    uint32_t a;
    asm("{ .reg .u64 t; cvta.to.shared.u64 t, %1; cvt.u32.u64 %0, t; }" : "=r"(a) : "l"(p));
    return a;
}
__device__ __forceinline__ void ldm4(uint32_t a, uint32_t* r) {
    asm volatile("ldmatrix.sync.aligned.m8n8.x4.shared.b16 {%0,%1,%2,%3}, [%4];"
                 : "=r"(r[0]), "=r"(r[1]), "=r"(r[2]), "=r"(r[3]) : "r"(a));
}
__device__ __forceinline__ void ldm4t(uint32_t a, uint32_t* r) {
    asm volatile("ldmatrix.sync.aligned.m8n8.x4.trans.shared.b16 {%0,%1,%2,%3}, [%4];"
                 : "=r"(r[0]), "=r"(r[1]), "=r"(r[2]), "=r"(r[3]) : "r"(a));
}
#define MMA4(D, A, B0, B1) \
    asm volatile("mma.sync.aligned.m16n8k16.row.col.f32.bf16.bf16.f32 " \
        "{%0,%1,%2,%3},{%4,%5,%6,%7},{%8,%9},{%0,%1,%2,%3};" \
        : "+f"((D)[0]), "+f"((D)[1]), "+f"((D)[2]), "+f"((D)[3]) \
        : "r"((A)[0]), "r"((A)[1]), "r"((A)[2]), "r"((A)[3]), "r"(B0), "r"(B1))

__device__ __forceinline__ uint32_t bpack(__nv_bfloat16 a, __nv_bfloat16 b) {
    __nv_bfloat162 t = __halves2bfloat162(a, b);
    return *reinterpret_cast<uint32_t*>(&t);
}
__device__ __forceinline__ void split2(float a, float b, uint32_t& h, uint32_t& l) {
    __nv_bfloat16 ha = __float2bfloat16(a), hb = __float2bfloat16(b);
    h = bpack(ha, hb);
    l = bpack(__float2bfloat16(a - __bfloat162float(ha)),
              __float2bfloat16(b - __bfloat162float(hb)));
}

// ---- prep: build B-fragments (hi/lo) + transposed conv weights ----
__global__ void prep_w(const float* __restrict__ qkv_w, const float* __restrict__ out_w,
                       const float* __restrict__ conv_w) {
    int e = blockIdx.x * 256 + threadIdx.x;
    if (e < 4608) {                       // 4 chunks x 6 k x 6 ni x 32 lanes
        int lane = e & 31; int t = e >> 5;
        int ni = t % 6; t /= 6; int k = t % 6; int c = t / 6;
        const float* W = (c < 3 ? qkv_w + c * 9216 : out_w);
        int n0 = ni * 16 + (lane >> 2), n1 = n0 + 8;
        int kk = k * 16 + (lane & 3) * 2;
        uint32_t h0,l0,h1,l1,h2,l2,h3,l3;
        split2(W[n0*96+kk],   W[n0*96+kk+1], h0, l0);
        split2(W[n1*96+kk],   W[n1*96+kk+1], h1, l1);
        split2(W[n0*96+kk+8], W[n0*96+kk+9], h2, l2);
        split2(W[n1*96+kk+8], W[n1*96+kk+9], h3, l3);
        g_wf[c][k][ni][0][lane] = make_uint4(h0, h1, h2, h3);
        g_wf[c][k][ni][1][lane] = make_uint4(l0, l1, l2, l3);
    } else if (e < 4608 + 864) {
        int i = e - 4608;                 // conv_w [ch][tap] -> g_cw [tap][ch]
        int ch = i / 9, tap = i - ch * 9;
        g_cw[tap][ch] = conv_w[i];
    }
}

__global__ __launch_bounds__(128, 4)
void vitblock_mma(const float* __restrict__ x,
                  const float* __restrict__ qkv_b,
                  const float* __restrict__ conv_b,
                  const float* __restrict__ out_b,
                  float* __restrict__ out)
{
    extern __shared__ char smem[];
    const uint32_t sb = smem_u32(smem);
    const int tid = threadIdx.x;
    const int w = tid >> 5, lane = tid & 31;
    const int lr = lane & 15, lc = lane >> 4;
    const int c2 = (lane & 3) * 2;
    const int r0 = 16 * w + (lane >> 2);
    const int mw = w >> 1, nw = w & 1;    // 2x2 warp tiling for K/V GEMMs

    const int wv0 = blockIdx.x & 31;
    const int wh  = (blockIdx.x >> 5) & 31;
    const int bI  = blockIdx.x >> 10;
    const float* xg = x + ((size_t)bI * 96) * 65536 + (size_t)(wh * 8) * 256 + wv0 * 8;

    // ---- stage X hi/lo ----
    #pragma unroll
    for (int it = 0; it < 12; it++) {
        int e = it * 128 + tid;          // 1536 = 24 c4 x 64 tok
        int c4 = e >> 6, t = e & 63;
        const float* p = xg + (size_t)(c4 * 4) * 65536 + (t >> 3) * 256 + (t & 7);
        float v0 = p[0], v1 = p[65536], v2 = p[131072], v3 = p[196608];
        __nv_bfloat16 h0 = __float2bfloat16(v0), h1 = __float2bfloat16(v1);
        __nv_bfloat16 h2 = __float2bfloat16(v2), h3 = __float2bfloat16(v3);
        uint2 H = { bpack(h0, h1), bpack(h2, h3) };
        uint2 L = { bpack(__float2bfloat16(v0 - __bfloat162float(h0)),
                          __float2bfloat16(v1 - __bfloat162float(h1))),
                    bpack(__float2bfloat16(v2 - __bfloat162float(h2)),
                          __float2bfloat16(v3 - __bfloat162float(h3))) };
        uint32_t off = (uint32_t)(t * XS + c4 * 4) << 1;
        *(uint2*)(smem + O_X + off) = H;
        *(uint2*)(smem + O_X + XLO2 + off) = L;
    }
    __syncthreads();

    // ---- GEMM K (single-pass bf16, 2x2 warp tiling) ----
    {
        float dk[2][6][4];
        #pragma unroll
        for (int a = 0; a < 2; a++)
            #pragma unroll
            for (int j = 0; j < 6; j++) { dk[a][j][0]=0.f; dk[a][j][1]=0.f; dk[a][j][2]=0.f; dk[a][j][3]=0.f; }
        #pragma unroll
        for (int k = 0; k < 6; k++) {
            uint32_t ah[2][4];
            #pragma unroll
            for (int mi = 0; mi < 2; mi++)
                ldm4(sb + O_X + (((mw * 32 + mi * 16 + lr) * XS + k * 16 + lc * 8) << 1), ah[mi]);
            #pragma unroll
            for (int ni = 0; ni < 3; ni++) {
                uint4 BH = __ldg(&g_wf[1][k][nw * 3 + ni][0][lane]);
                #pragma unroll
                for (int mi = 0; mi < 2; mi++) {
                    MMA4(dk[mi][2*ni],   ah[mi], BH.x, BH.z);
                    MMA4(dk[mi][2*ni+1], ah[mi], BH.y, BH.w);
                }
            }
        }
        #pragma unroll
        for (int mi = 0; mi < 2; mi++)
            #pragma unroll
            for (int j = 0; j < 6; j++) {
                int col = nw * 48 + 8 * j + c2;
                float2 bk = __ldg((const float2*)(qkv_b + 96 + col));
                #pragma unroll
                for (int h = 0; h < 2; h++) {
                    int row = mw * 32 + mi * 16 + (lane >> 2) + 8 * h;
                    uint32_t hh = bpack(__float2bfloat16(dk[mi][j][2*h]   + bk.x),
                                        __float2bfloat16(dk[mi][j][2*h+1] + bk.y));
                    *(uint32_t*)(smem + O_K + ((uint32_t)(row * XS + col) << 1)) = hh;
                }
            }
    }

    // ---- GEMM Q (single-pass bf16; fragments stay in registers) ----
    uint32_t qh[6][4];
    {
        float dq[12][4];
        #pragma unroll
        for (int j = 0; j < 12; j++) { dq[j][0]=0.f; dq[j][1]=0.f; dq[j][2]=0.f; dq[j][3]=0.f; }
        #pragma unroll
        for (int k = 0; k < 6; k++) {
            uint32_t ah[4];
            ldm4(sb + O_X + (((16 * w + lr) * XS + k * 16 + lc * 8) << 1), ah);
            #pragma unroll
            for (int ni = 0; ni < 6; ni++) {
                uint4 BH = __ldg(&g_wf[0][k][ni][0][lane]);
                MMA4(dq[2*ni],   ah, BH.x, BH.z);
                MMA4(dq[2*ni+1], ah, BH.y, BH.w);
            }
        }
        #pragma unroll
        for (int jj = 0; jj < 6; jj++) {
            int ta = 2 * jj, tb = 2 * jj + 1;
            float2 ba = __ldg((const float2*)(qkv_b + 8 * ta + c2));
            float2 bb = __ldg((const float2*)(qkv_b + 8 * tb + c2));
            qh[jj][0] = bpack(__float2bfloat16((dq[ta][0] + ba.x) * SCALE_Q),
                              __float2bfloat16((dq[ta][1] + ba.y) * SCALE_Q));
            qh[jj][1] = bpack(__float2bfloat16((dq[ta][2] + ba.x) * SCALE_Q),
                              __float2bfloat16((dq[ta][3] + ba.y) * SCALE_Q));
            qh[jj][2] = bpack(__float2bfloat16((dq[tb][0] + bb.x) * SCALE_Q),
                              __float2bfloat16((dq[tb][1] + bb.y) * SCALE_Q));
            qh[jj][3] = bpack(__float2bfloat16((dq[tb][2] + bb.x) * SCALE_Q),
                              __float2bfloat16((dq[tb][3] + bb.y) * SCALE_Q));
        }
    }

    // ---- GEMM V (3-term, 2x2 warp tiling) ----
    float dv[2][6][4];
    #pragma unroll
    for (int a = 0; a < 2; a++)
        #pragma unroll
        for (int j = 0; j < 6; j++) { dv[a][j][0]=0.f; dv[a][j][1]=0.f; dv[a][j][2]=0.f; dv[a][j][3]=0.f; }
    #pragma unroll
    for (int k = 0; k < 6; k++) {
        uint32_t ah[2][4], al[2][4];
        #pragma unroll
        for (int mi = 0; mi < 2; mi++) {
            uint32_t aa = sb + O_X + (((mw * 32 + mi * 16 + lr) * XS + k * 16 + lc * 8) << 1);
            ldm4(aa, ah[mi]);
            ldm4(aa + XLO2, al[mi]);
        }
        #pragma unroll
        for (int ni = 0; ni < 3; ni++) {
            uint4 BH = __ldg(&g_wf[2][k][nw * 3 + ni][0][lane]);
            uint4 BL = __ldg(&g_wf[2][k][nw * 3 + ni][1][lane]);
            #pragma unroll
            for (int mi = 0; mi < 2; mi++) {
                MMA4(dv[mi][2*ni],   ah[mi], BH.x, BH.z);
                MMA4(dv[mi][2*ni+1], ah[mi], BH.y, BH.w);
                MMA4(dv[mi][2*ni],   ah[mi], BL.x, BL.z);
                MMA4(dv[mi][2*ni+1], ah[mi], BL.y, BL.w);
                MMA4(dv[mi][2*ni],   al[mi], BH.x, BH.z);
                MMA4(dv[mi][2*ni+1], al[mi], BH.y, BH.w);
            }
        }
    }
    __syncthreads();                    // all warps done reading X
    // write V hi/lo into X region (tok-major)
    #pragma unroll
    for (int mi = 0; mi < 2; mi++)
        #pragma unroll
        for (int j = 0; j < 6; j++) {
            int col = nw * 48 + 8 * j + c2;
            float2 bv = __ldg((const float2*)(qkv_b + 192 + col));
            #pragma unroll
            for (int h = 0; h < 2; h++) {
                int row = mw * 32 + mi * 16 + (lane >> 2) + 8 * h;
                uint32_t hh, ll;
                split2(dv[mi][j][2*h] + bv.x, dv[mi][j][2*h+1] + bv.y, hh, ll);
                uint32_t o0 = (uint32_t)(row * XS + col) << 1;
                *(uint32_t*)(smem + O_X + o0) = hh;
                *(uint32_t*)(smem + O_X + XLO2 + o0) = ll;
            }
        }
    __syncthreads();                    // V + K visible to all warps

    // ---- scores S = Q'K^T (single-pass bf16) ----
    float s[8][4];
    #pragma unroll
    for (int j = 0; j < 8; j++) { s[j][0]=0.f; s[j][1]=0.f; s[j][2]=0.f; s[j][3]=0.f; }
    #pragma unroll
    for (int k = 0; k < 6; k++) {
        #pragma unroll
        for (int np = 0; np < 4; np++) {
            uint32_t bh[4];
            ldm4(sb + O_K + (((np * 16 + lr) * XS + k * 16 + lc * 8) << 1), bh);
            MMA4(s[2*np],   qh[k], bh[0], bh[2]);
            MMA4(s[2*np+1], qh[k], bh[1], bh[3]);
        }
    }

    // ---- softmax in registers ----
    {
        float mx0 = -1e30f, mx1 = -1e30f;
        #pragma unroll
        for (int j = 0; j < 8; j++) {
            mx0 = fmaxf(mx0, fmaxf(s[j][0], s[j][1]));
            mx1 = fmaxf(mx1, fmaxf(s[j][2], s[j][3]));
        }
        mx0 = fmaxf(mx0, __shfl_xor_sync(0xffffffffu, mx0, 1));
        mx0 = fmaxf(mx0, __shfl_xor_sync(0xffffffffu, mx0, 2));
        mx1 = fmaxf(mx1, __shfl_xor_sync(0xffffffffu, mx1, 1));
        mx1 = fmaxf(mx1, __shfl_xor_sync(0xffffffffu, mx1, 2));
        float s0 = 0.f, s1 = 0.f;
        #pragma unroll
        for (int j = 0; j < 8; j++) {
            s[j][0] = __expf(s[j][0] - mx0); s[j][1] = __expf(s[j][1] - mx0);
            s[j][2] = __expf(s[j][2] - mx1); s[j][3] = __expf(s[j][3] - mx1);
            s0 += s[j][0] + s[j][1];
            s1 += s[j][2] + s[j][3];
        }
        s0 += __shfl_xor_sync(0xffffffffu, s0, 1);
        s0 += __shfl_xor_sync(0xffffffffu, s0, 2);
        s1 += __shfl_xor_sync(0xffffffffu, s1, 1);
        s1 += __shfl_xor_sync(0xffffffffu, s1, 2);
        float i0 = 1.0f / s0, i1 = 1.0f / s1;
        #pragma unroll
        for (int j = 0; j < 8; j++) {
            s[j][0] *= i0; s[j][1] *= i0; s[j][2] *= i1; s[j][3] *= i1;
        }
    }
    uint32_t ph[4][4], pl[4][4];
    #pragma unroll
    for (int jj = 0; jj < 4; jj++) {
        split2(s[2*jj][0],   s[2*jj][1],   ph[jj][0], pl[jj][0]);
        split2(s[2*jj][2],   s[2*jj][3],   ph[jj][1], pl[jj][1]);
        split2(s[2*jj+1][0], s[2*jj+1][1], ph[jj][2], pl[jj][2]);
        split2(s[2*jj+1][2], s[2*jj+1][3], ph[jj][3], pl[jj][3]);
    }

    // ---- PV: O = P @ V  (V tok-major in X region, ldmatrix.trans, 3-term) ----
    float o[12][4];
    #pragma unroll
    for (int j = 0; j < 12; j++) { o[j][0]=0.f; o[j][1]=0.f; o[j][2]=0.f; o[j][3]=0.f; }
    {
        const int g = lane >> 3;
        const int tokoff = ((g >> 1) << 3) + (lane & 7);
        const int choff  = (g & 1) << 3;
        #pragma unroll
        for (int k = 0; k < 4; k++) {
            #pragma unroll
            for (int nb = 0; nb < 6; nb++) {
                uint32_t bh[4], bl[4];
                uint32_t ba = sb + O_X + (((k * 16 + tokoff) * XS + nb * 16 + choff) << 1);
                ldm4t(ba, bh);
                ldm4t(ba + XLO2, bl);
                MMA4(o[2*nb],   ph[k], bh[0], bh[2]);
                MMA4(o[2*nb+1], ph[k], bh[1], bh[3]);
                MMA4(o[2*nb],   ph[k], bl[0], bl[2]);
                MMA4(o[2*nb+1], ph[k], bl[1], bl[3]);
                MMA4(o[2*nb],   pl[k], bh[0], bh[2]);
                MMA4(o[2*nb+1], pl[k], bh[1], bh[3]);
            }
        }
    }

    // ---- O' = O + LePE + conv_b (v from V hi+lo); repack to A-frags ----
    uint32_t oh[6][4], ol[6][4];
    {
        #pragma unroll
        for (int j = 0; j < 12; j++) {
            int c0 = 8 * j + c2;
            float2 cb2 = __ldg((const float2*)(conv_b + c0));
            #pragma unroll
            for (int h = 0; h < 2; h++) {
                int row = r0 + 8 * h;
                int y = row >> 3, xx = row & 7;
                float ax = o[j][2*h] + cb2.x, ay = o[j][2*h+1] + cb2.y;
                #pragma unroll
                for (int dy = -1; dy <= 1; dy++) {
                    int yy = y + dy;
                    if ((unsigned)yy > 7u) continue;
                    #pragma unroll
                    for (int dx = -1; dx <= 1; dx++) {
                        int xc = xx + dx;
                        if ((unsigned)xc > 7u) continue;
                        int nb = yy * 8 + xc;
                        uint32_t off = (uint32_t)(nb * XS + c0) << 1;
                        __nv_bfloat162 hv = *(__nv_bfloat162*)(smem + O_X + off);
                        __nv_bfloat162 lv = *(__nv_bfloat162*)(smem + O_X + XLO2 + off);
                        float2 cw = __ldg((const float2*)&g_cw[(dy + 1) * 3 + (dx + 1)][c0]);
                        ax += (__bfloat162float(hv.x) + __bfloat162float(lv.x)) * cw.x;
                        ay += (__bfloat162float(hv.y) + __bfloat162float(lv.y)) * cw.y;
                    }
                }
                o[j][2*h] = ax; o[j][2*h+1] = ay;
            }
        }
        #pragma unroll
        for (int jj = 0; jj < 6; jj++) {
            split2(o[2*jj][0],   o[2*jj][1],   oh[jj][0], ol[jj][0]);
            split2(o[2*jj][2],   o[2*jj][3],   oh[jj][1], ol[jj][1]);
            split2(o[2*jj+1][0], o[2*jj+1][1], oh[jj][2], ol[jj][2]);
            split2(o[2*jj+1][2], o[2*jj+1][3], oh[jj][3], ol[jj][3]);
        }
    }

    // ---- GEMM3: out = O' @ out_w^T + out_b (3-term, A in regs) ----
    float f[12][4];
    #pragma unroll
    for (int j = 0; j < 12; j++) { f[j][0]=0.f; f[j][1]=0.f; f[j][2]=0.f; f[j][3]=0.f; }
    #pragma unroll
    for (int k = 0; k < 6; k++) {
        #pragma unroll
        for (int ni = 0; ni < 6; ni++) {
            uint4 BH = __ldg(&g_wf[3][k][ni][0][lane]);
            uint4 BL = __ldg(&g_wf[3][k][ni][1][lane]);
            MMA4(f[2*ni],   oh[k], BH.x, BH.z);
            MMA4(f[2*ni+1], oh[k], BH.y, BH.w);
            MMA4(f[2*ni],   oh[k], BL.x, BL.z);
            MMA4(f[2*ni+1], oh[k], BL.y, BL.w);
            MMA4(f[2*ni],   ol[k], BH.x, BH.z);
            MMA4(f[2*ni+1], ol[k], BH.y, BH.w);
        }
    }
    __syncthreads();                    // V region dead (PV+LePE done) -> outstage
    #pragma unroll
    for (int j = 0; j < 12; j++) {
        float2 bo = __ldg((const float2*)(out_b + 8 * j + c2));
        float2 a = { f[j][0] + bo.x, f[j][1] + bo.y };
        float2 b = { f[j][2] + bo.x, f[j][3] + bo.y };
        *(float2*)(smem + O_X + ((r0 * FS + 8 * j + c2) << 2)) = a;
        *(float2*)(smem + O_X + (((r0 + 8) * FS + 8 * j + c2) << 2)) = b;
    }
    __syncthreads();

    // ---- coalesced writeout ----
    float* og = out + ((size_t)bI * 96) * 65536 + (size_t)(wh * 8) * 256 + wv0 * 8;
    #pragma unroll
    for (int it = 0; it < 12; it++) {
        int e = it * 128 + tid;
        int c4 = e >> 6, t = e & 63;
        const float* st = (const float*)(smem + O_X) + t * FS + c4 * 4;
        float2 u = *(const float2*)st;
        float2 v = *(const float2*)(st + 2);
        float* g = og + (size_t)(c4 * 4) * 65536 + (t >> 3) * 256 + (t & 7);
        g[0] = u.x; g[65536] = u.y; g[131072] = v.x; g[196608] = v.y;
    }
}

extern "C" void kernel_launch(void* const* d_in, const int* in_sizes, int n_in,
                              void* d_out, int out_size) {
    const float* x      = (const float*)d_in[0];
    const float* qkv_w  = (const float*)d_in[1];
    const float* qkv_b  = (const float*)d_in[2];
    const float* conv_w = (const float*)d_in[3];
    const float* conv_b = (const float*)d_in[4];
    const float* out_w  = (const float*)d_in[5];
    const float* out_b  = (const float*)d_in[6];
    float* out = (float*)d_out;

    prep_w<<<22, 256>>>(qkv_w, out_w, conv_w);
    cudaFuncSetAttribute(vitblock_mma,
                         cudaFuncAttributeMaxDynamicSharedMemorySize, SMEM_BYTES);
    vitblock_mma<<<8192, 128, SMEM_BYTES>>>(x, qkv_b, conv_b, out_b, out);
}